// round 1
// baseline (speedup 1.0000x reference)
#include <cuda_runtime.h>
#include <math.h>

// Problem constants
#define NTOK 4096          // B*(H/2)*(W/2) = 16*16*16
#define DDIM 512           // C*p*p
#define NEXP 8
#define HID  1024
#define NPAIR (NTOK * 2)   // top-2 -> 8192 token-expert pairs
#define CC   128
#define HH   32
#define WW   32

// ---------------- static device scratch (no allocations allowed) -------------
__device__ float d_xp[NTOK * DDIM];          // patchified tokens [4096,512]  8 MB
__device__ float d_he[NPAIR * HID];          // swiglu activations [8192,1024] 32 MB
__device__ float d_po[NPAIR * DDIM];         // gate-scaled expert outputs [8192,512] 16 MB
__device__ int   d_counts[NEXP];
__device__ int   d_offsets[NEXP];
__device__ int   d_tok_e[NTOK * 2];
__device__ int   d_tok_r[NTOK * 2];
__device__ float d_tok_g[NTOK * 2];
__device__ int   d_tok_pr[NTOK * 2];
__device__ int   d_row_token[NPAIR];
__device__ float d_row_gate[NPAIR];

// ---------------- reset ------------------------------------------------------
__global__ void reset_kernel() {
    int t = threadIdx.x;
    if (t < NEXP) d_counts[t] = 0;
}

// ---------------- patchify: x[B,C,H,W] -> xp[N,d] ----------------------------
__global__ void patchify_kernel(const float* __restrict__ x) {
    int idx = blockIdx.x * blockDim.x + threadIdx.x;
    if (idx >= NTOK * DDIM) return;
    int n = idx >> 9;            // /512
    int d = idx & 511;
    int b  = n >> 8;             // /256
    int h2 = (n >> 4) & 15;
    int w2 = n & 15;
    int c  = d >> 2;
    int ph = (d >> 1) & 1;
    int pw = d & 1;
    d_xp[idx] = x[(((b * CC + c) * HH) + h2 * 2 + ph) * WW + w2 * 2 + pw];
}

// ---------------- router: logits, top-2, gates, expert counters --------------
// one warp per token; router_w cached transposed in smem
__global__ void router_kernel(const float* __restrict__ rw) {
    __shared__ float rwT[NEXP * DDIM];   // rwT[e*512 + k]
    int tid = threadIdx.x;
    for (int i = tid; i < NEXP * DDIM; i += blockDim.x) {
        int k = i >> 3, e = i & 7;
        rwT[e * DDIM + k] = rw[i];
    }
    __syncthreads();

    int warp = tid >> 5, lane = tid & 31;
    int n = blockIdx.x * 8 + warp;
    if (n >= NTOK) return;

    const float* xr = d_xp + (size_t)n * DDIM;
    float acc[NEXP];
#pragma unroll
    for (int e = 0; e < NEXP; e++) acc[e] = 0.f;

#pragma unroll
    for (int t = 0; t < DDIM / 32; t++) {
        int k = lane + t * 32;
        float xv = xr[k];
#pragma unroll
        for (int e = 0; e < NEXP; e++) acc[e] += xv * rwT[e * DDIM + k];
    }
#pragma unroll
    for (int e = 0; e < NEXP; e++) {
#pragma unroll
        for (int off = 16; off > 0; off >>= 1)
            acc[e] += __shfl_xor_sync(0xFFFFFFFFu, acc[e], off);
    }
    if (lane == 0) {
        int i0 = 0; float l0 = acc[0];
#pragma unroll
        for (int e = 1; e < NEXP; e++) if (acc[e] > l0) { l0 = acc[e]; i0 = e; }
        int i1 = -1; float l1 = -1e30f;
#pragma unroll
        for (int e = 0; e < NEXP; e++) if (e != i0 && acc[e] > l1) { l1 = acc[e]; i1 = e; }
        // softmax + top2 renorm == softmax over the two top logits
        float g0 = 1.f / (1.f + expf(l1 - l0));
        float g1 = 1.f - g0;
        int r0 = atomicAdd(&d_counts[i0], 1);
        int r1 = atomicAdd(&d_counts[i1], 1);
        d_tok_e[n * 2 + 0] = i0; d_tok_r[n * 2 + 0] = r0; d_tok_g[n * 2 + 0] = g0;
        d_tok_e[n * 2 + 1] = i1; d_tok_r[n * 2 + 1] = r1; d_tok_g[n * 2 + 1] = g1;
    }
}

// ---------------- exclusive prefix over 8 counts -----------------------------
__global__ void offsets_kernel() {
    int s = 0;
    for (int e = 0; e < NEXP; e++) { d_offsets[e] = s; s += d_counts[e]; }
}

// ---------------- scatter token -> expert row lists --------------------------
__global__ void scatter_kernel() {
    int n = blockIdx.x * blockDim.x + threadIdx.x;
    if (n >= NTOK) return;
#pragma unroll
    for (int j = 0; j < 2; j++) {
        int e = d_tok_e[n * 2 + j];
        int pr = d_offsets[e] + d_tok_r[n * 2 + j];
        d_row_token[pr] = n;
        d_row_gate[pr]  = d_tok_g[n * 2 + j];
        d_tok_pr[n * 2 + j] = pr;
    }
}

// ---------------- GEMM1 + SwiGLU: he[r,:] = val * sigmoid(g) -----------------
// A = gathered xp rows [cnt,512], B = w1[e] [512,2048] (cols j and j+1024)
// tile 64x64x16, 128 threads, each thread 4x8 outputs for val AND gate
__global__ void __launch_bounds__(128) gemm1_kernel(const float* __restrict__ w1) {
    int e = blockIdx.z;
    int cnt = d_counts[e];
    int row0 = blockIdx.y * 64;
    if (row0 >= cnt) return;
    int base = d_offsets[e];
    int jn0 = blockIdx.x * 64;

    __shared__ float As[16][68];     // transposed [k][m], padded
    __shared__ float Bv[16][64];
    __shared__ float Bg[16][64];
    __shared__ int   rows_s[64];

    int tid = threadIdx.x;
    if (tid < 64) {
        int rr = row0 + tid;
        rows_s[tid] = d_row_token[base + ((rr < cnt) ? rr : (cnt - 1))];
    }
    __syncthreads();

    const float* w1e = w1 + (size_t)e * DDIM * (2 * HID);

    float accV[4][8], accG[4][8];
#pragma unroll
    for (int i = 0; i < 4; i++)
#pragma unroll
        for (int j = 0; j < 8; j++) { accV[i][j] = 0.f; accG[i][j] = 0.f; }

    int ty = tid >> 3;               // 0..15 -> row group (4 rows)
    int tx = tid & 7;                // 0..7  -> col group (8 cols)
    int a_r = tid >> 2;              // 0..31
    int a_c = (tid & 3) << 2;        // float4 col within 16

    for (int k0 = 0; k0 < DDIM; k0 += 16) {
        // load A (gathered), store transposed
#pragma unroll
        for (int it = 0; it < 2; it++) {
            int r = a_r + it * 32;
            float4 v = *(const float4*)(d_xp + (size_t)rows_s[r] * DDIM + k0 + a_c);
            As[a_c + 0][r] = v.x; As[a_c + 1][r] = v.y;
            As[a_c + 2][r] = v.z; As[a_c + 3][r] = v.w;
        }
        // load B (val and gate halves)
#pragma unroll
        for (int it = 0; it < 2; it++) {
            int idx = tid + it * 128;
            int kk = idx >> 4;
            int c4 = (idx & 15) << 2;
            const float* bp = w1e + (size_t)(k0 + kk) * (2 * HID) + jn0 + c4;
            *(float4*)&Bv[kk][c4] = *(const float4*)bp;
            *(float4*)&Bg[kk][c4] = *(const float4*)(bp + HID);
        }
        __syncthreads();
#pragma unroll
        for (int kk = 0; kk < 16; kk++) {
            float4 a4 = *(const float4*)&As[kk][ty * 4];
            float a[4] = {a4.x, a4.y, a4.z, a4.w};
            float4 v0 = *(const float4*)&Bv[kk][tx * 8];
            float4 v1 = *(const float4*)&Bv[kk][tx * 8 + 4];
            float4 g0 = *(const float4*)&Bg[kk][tx * 8];
            float4 g1 = *(const float4*)&Bg[kk][tx * 8 + 4];
            float bv[8] = {v0.x, v0.y, v0.z, v0.w, v1.x, v1.y, v1.z, v1.w};
            float bg[8] = {g0.x, g0.y, g0.z, g0.w, g1.x, g1.y, g1.z, g1.w};
#pragma unroll
            for (int i = 0; i < 4; i++)
#pragma unroll
                for (int j = 0; j < 8; j++) {
                    accV[i][j] += a[i] * bv[j];
                    accG[i][j] += a[i] * bg[j];
                }
        }
        __syncthreads();
    }

    // epilogue: SwiGLU
#pragma unroll
    for (int i = 0; i < 4; i++) {
        int rloc = ty * 4 + i;
        int r = row0 + rloc;
        if (r >= cnt) continue;
        float out[8];
#pragma unroll
        for (int j = 0; j < 8; j++) {
            float s = 1.f / (1.f + expf(-accG[i][j]));
            out[j] = accV[i][j] * s;
        }
        float* hp = d_he + (size_t)(base + r) * HID + jn0 + tx * 8;
        *(float4*)(hp)     = make_float4(out[0], out[1], out[2], out[3]);
        *(float4*)(hp + 4) = make_float4(out[4], out[5], out[6], out[7]);
    }
}

// ---------------- GEMM2: po[r,:] = gate[r] * (he[r,:] @ w2[e]) ---------------
__global__ void __launch_bounds__(128) gemm2_kernel(const float* __restrict__ w2) {
    int e = blockIdx.z;
    int cnt = d_counts[e];
    int row0 = blockIdx.y * 64;
    if (row0 >= cnt) return;
    int base = d_offsets[e];
    int n0 = blockIdx.x * 64;

    __shared__ float As[16][68];
    __shared__ float Bs[16][64];
    __shared__ float gate_s[64];

    int tid = threadIdx.x;
    if (tid < 64) {
        int rr = row0 + tid;
        gate_s[tid] = (rr < cnt) ? d_row_gate[base + rr] : 0.f;
    }

    const float* w2e = w2 + (size_t)e * HID * DDIM;

    float acc[4][8];
#pragma unroll
    for (int i = 0; i < 4; i++)
#pragma unroll
        for (int j = 0; j < 8; j++) acc[i][j] = 0.f;

    int ty = tid >> 3;
    int tx = tid & 7;
    int a_r = tid >> 2;
    int a_c = (tid & 3) << 2;

    for (int k0 = 0; k0 < HID; k0 += 16) {
#pragma unroll
        for (int it = 0; it < 2; it++) {
            int r = a_r + it * 32;
            int rr = row0 + r; if (rr >= cnt) rr = cnt - 1;   // clamp (valid data)
            float4 v = *(const float4*)(d_he + (size_t)(base + rr) * HID + k0 + a_c);
            As[a_c + 0][r] = v.x; As[a_c + 1][r] = v.y;
            As[a_c + 2][r] = v.z; As[a_c + 3][r] = v.w;
        }
#pragma unroll
        for (int it = 0; it < 2; it++) {
            int idx = tid + it * 128;
            int kk = idx >> 4;
            int c4 = (idx & 15) << 2;
            *(float4*)&Bs[kk][c4] =
                *(const float4*)(w2e + (size_t)(k0 + kk) * DDIM + n0 + c4);
        }
        __syncthreads();
#pragma unroll
        for (int kk = 0; kk < 16; kk++) {
            float4 a4 = *(const float4*)&As[kk][ty * 4];
            float a[4] = {a4.x, a4.y, a4.z, a4.w};
            float4 b0 = *(const float4*)&Bs[kk][tx * 8];
            float4 b1 = *(const float4*)&Bs[kk][tx * 8 + 4];
            float b[8] = {b0.x, b0.y, b0.z, b0.w, b1.x, b1.y, b1.z, b1.w};
#pragma unroll
            for (int i = 0; i < 4; i++)
#pragma unroll
                for (int j = 0; j < 8; j++) acc[i][j] += a[i] * b[j];
        }
        __syncthreads();
    }

#pragma unroll
    for (int i = 0; i < 4; i++) {
        int rloc = ty * 4 + i;
        int r = row0 + rloc;
        if (r >= cnt) continue;
        float g = gate_s[rloc];
        float* pp = d_po + (size_t)(base + r) * DDIM + n0 + tx * 8;
        *(float4*)(pp)     = make_float4(g * acc[i][0], g * acc[i][1], g * acc[i][2], g * acc[i][3]);
        *(float4*)(pp + 4) = make_float4(g * acc[i][4], g * acc[i][5], g * acc[i][6], g * acc[i][7]);
    }
}

// ---------------- combine two expert outputs + unpatchify --------------------
__global__ void combine_kernel(float* __restrict__ y) {
    int idx = blockIdx.x * blockDim.x + threadIdx.x;
    if (idx >= NTOK * DDIM) return;
    int w = idx & 31;
    int h = (idx >> 5) & 31;
    int c = (idx >> 10) & 127;
    int b = idx >> 17;
    int n = (b << 8) + ((h >> 1) << 4) + (w >> 1);
    int d = (c << 2) + ((h & 1) << 1) + (w & 1);
    int pr0 = d_tok_pr[n * 2 + 0];
    int pr1 = d_tok_pr[n * 2 + 1];
    y[idx] = d_po[(size_t)pr0 * DDIM + d] + d_po[(size_t)pr1 * DDIM + d];
}

// ---------------- launch -----------------------------------------------------
extern "C" void kernel_launch(void* const* d_in, const int* in_sizes, int n_in,
                              void* d_out, int out_size) {
    const float* x  = (const float*)d_in[0];
    const float* rw = (const float*)d_in[1];
    const float* w1 = (const float*)d_in[2];
    const float* w2 = (const float*)d_in[3];
    float* y = (float*)d_out;

    reset_kernel<<<1, 32>>>();
    patchify_kernel<<<(NTOK * DDIM + 255) / 256, 256>>>(x);
    router_kernel<<<NTOK / 8, 256>>>(rw);
    offsets_kernel<<<1, 1>>>();
    scatter_kernel<<<(NTOK + 255) / 256, 256>>>();

    dim3 g1(2 * HID / 2 / 64, NTOK / 64, NEXP);   // (16, 64, 8)
    gemm1_kernel<<<g1, 128>>>(w1);
    dim3 g2(DDIM / 64, NTOK / 64, NEXP);          // (8, 64, 8)
    gemm2_kernel<<<g2, 128>>>(w2);

    combine_kernel<<<(NTOK * DDIM + 255) / 256, 256>>>(y);
}

// round 2
// speedup vs baseline: 1.0076x; 1.0076x over previous
#include <cuda_runtime.h>
#include <math.h>

// Problem constants
#define NTOK 4096          // B*(H/2)*(W/2) = 16*16*16
#define DDIM 512           // C*p*p
#define NEXP 8
#define HID  1024
#define NPAIR (NTOK * 2)   // top-2 -> 8192 token-expert pairs
#define CC   128
#define HH   32
#define WW   32

// ---------------- static device scratch (no allocations allowed) -------------
__device__ float d_xp[NTOK * DDIM];          // patchified tokens [4096,512]
__device__ float d_he[NPAIR * HID];          // swiglu activations [8192,1024]
__device__ float d_po[NPAIR * DDIM];         // gate-scaled expert outputs [8192,512]
__device__ int   d_counts[NEXP];
__device__ int   d_offsets[NEXP];
__device__ int   d_tok_e[NTOK * 2];
__device__ int   d_tok_r[NTOK * 2];
__device__ float d_tok_g[NTOK * 2];
__device__ int   d_tok_pr[NTOK * 2];
__device__ int   d_row_token[NPAIR];
__device__ float d_row_gate[NPAIR];

// ---------------- packed f32x2 helpers (Blackwell FFMA2 path) ----------------
typedef unsigned long long u64t;

__device__ __forceinline__ void ffma2(u64t& d, u64t a, u64t b) {
    // d = a * b + d   lane-wise on packed {f32,f32}; exact fp32 semantics
    asm("fma.rn.f32x2 %0, %1, %2, %0;" : "+l"(d) : "l"(a), "l"(b));
}
__device__ __forceinline__ u64t dup2(float x) {
    u64t r;
    asm("mov.b64 %0, {%1, %1};" : "=l"(r) : "f"(x));
    return r;
}
__device__ __forceinline__ void unpack2(float& lo, float& hi, u64t v) {
    asm("mov.b64 {%0, %1}, %2;" : "=f"(lo), "=f"(hi) : "l"(v));
}

// ---------------- reset ------------------------------------------------------
__global__ void reset_kernel() {
    int t = threadIdx.x;
    if (t < NEXP) d_counts[t] = 0;
}

// ---------------- patchify: x[B,C,H,W] -> xp[N,d] ----------------------------
__global__ void patchify_kernel(const float* __restrict__ x) {
    int idx = blockIdx.x * blockDim.x + threadIdx.x;
    if (idx >= NTOK * DDIM) return;
    int n = idx >> 9;            // /512
    int d = idx & 511;
    int b  = n >> 8;             // /256
    int h2 = (n >> 4) & 15;
    int w2 = n & 15;
    int c  = d >> 2;
    int ph = (d >> 1) & 1;
    int pw = d & 1;
    d_xp[idx] = x[(((b * CC + c) * HH) + h2 * 2 + ph) * WW + w2 * 2 + pw];
}

// ---------------- router: logits, top-2, gates, expert counters --------------
__global__ void router_kernel(const float* __restrict__ rw) {
    __shared__ float rwT[NEXP * DDIM];   // rwT[e*512 + k]
    int tid = threadIdx.x;
    for (int i = tid; i < NEXP * DDIM; i += blockDim.x) {
        int k = i >> 3, e = i & 7;
        rwT[e * DDIM + k] = rw[i];
    }
    __syncthreads();

    int warp = tid >> 5, lane = tid & 31;
    int n = blockIdx.x * 8 + warp;
    if (n >= NTOK) return;

    const float* xr = d_xp + (size_t)n * DDIM;
    float acc[NEXP];
#pragma unroll
    for (int e = 0; e < NEXP; e++) acc[e] = 0.f;

#pragma unroll
    for (int t = 0; t < DDIM / 32; t++) {
        int k = lane + t * 32;
        float xv = xr[k];
#pragma unroll
        for (int e = 0; e < NEXP; e++) acc[e] += xv * rwT[e * DDIM + k];
    }
#pragma unroll
    for (int e = 0; e < NEXP; e++) {
#pragma unroll
        for (int off = 16; off > 0; off >>= 1)
            acc[e] += __shfl_xor_sync(0xFFFFFFFFu, acc[e], off);
    }
    if (lane == 0) {
        int i0 = 0; float l0 = acc[0];
#pragma unroll
        for (int e = 1; e < NEXP; e++) if (acc[e] > l0) { l0 = acc[e]; i0 = e; }
        int i1 = -1; float l1 = -1e30f;
#pragma unroll
        for (int e = 0; e < NEXP; e++) if (e != i0 && acc[e] > l1) { l1 = acc[e]; i1 = e; }
        float g0 = 1.f / (1.f + expf(l1 - l0));
        float g1 = 1.f - g0;
        int r0 = atomicAdd(&d_counts[i0], 1);
        int r1 = atomicAdd(&d_counts[i1], 1);
        d_tok_e[n * 2 + 0] = i0; d_tok_r[n * 2 + 0] = r0; d_tok_g[n * 2 + 0] = g0;
        d_tok_e[n * 2 + 1] = i1; d_tok_r[n * 2 + 1] = r1; d_tok_g[n * 2 + 1] = g1;
    }
}

// ---------------- exclusive prefix over 8 counts -----------------------------
__global__ void offsets_kernel() {
    int s = 0;
    for (int e = 0; e < NEXP; e++) { d_offsets[e] = s; s += d_counts[e]; }
}

// ---------------- scatter token -> expert row lists --------------------------
__global__ void scatter_kernel() {
    int n = blockIdx.x * blockDim.x + threadIdx.x;
    if (n >= NTOK) return;
#pragma unroll
    for (int j = 0; j < 2; j++) {
        int e = d_tok_e[n * 2 + j];
        int pr = d_offsets[e] + d_tok_r[n * 2 + j];
        d_row_token[pr] = n;
        d_row_gate[pr]  = d_tok_g[n * 2 + j];
        d_tok_pr[n * 2 + j] = pr;
    }
}

// ---------------- GEMM1 + SwiGLU (FFMA2 packed) ------------------------------
// A = gathered xp rows [cnt,512], B = w1[e] [512,2048] (cols j and j+1024)
// tile 64x64x16, 128 threads, each thread 4 rows x 8 cols (as 4 f32x2 pairs)
__global__ void __launch_bounds__(128) gemm1_kernel(const float* __restrict__ w1) {
    int e = blockIdx.z;
    int cnt = d_counts[e];
    int row0 = blockIdx.y * 64;
    if (row0 >= cnt) return;
    int base = d_offsets[e];
    int jn0 = blockIdx.x * 64;

    __shared__ float As[16][68];     // transposed [k][m], padded
    __shared__ float Bv[16][64];
    __shared__ float Bg[16][64];
    __shared__ int   rows_s[64];

    int tid = threadIdx.x;
    if (tid < 64) {
        int rr = row0 + tid;
        rows_s[tid] = d_row_token[base + ((rr < cnt) ? rr : (cnt - 1))];
    }
    __syncthreads();

    const float* w1e = w1 + (size_t)e * DDIM * (2 * HID);

    u64t accV[4][4], accG[4][4];     // [row][col-pair], each holds 2 fp32 cols
#pragma unroll
    for (int i = 0; i < 4; i++)
#pragma unroll
        for (int j = 0; j < 4; j++) { accV[i][j] = 0ull; accG[i][j] = 0ull; }

    int ty = tid >> 3;               // 0..15 -> row group (4 rows)
    int tx = tid & 7;                // 0..7  -> col group (8 cols = 4 pairs)
    int a_r = tid >> 2;              // 0..31
    int a_c = (tid & 3) << 2;        // float4 col within 16

    for (int k0 = 0; k0 < DDIM; k0 += 16) {
#pragma unroll
        for (int it = 0; it < 2; it++) {
            int r = a_r + it * 32;
            float4 v = *(const float4*)(d_xp + (size_t)rows_s[r] * DDIM + k0 + a_c);
            As[a_c + 0][r] = v.x; As[a_c + 1][r] = v.y;
            As[a_c + 2][r] = v.z; As[a_c + 3][r] = v.w;
        }
#pragma unroll
        for (int it = 0; it < 2; it++) {
            int idx = tid + it * 128;
            int kk = idx >> 4;
            int c4 = (idx & 15) << 2;
            const float* bp = w1e + (size_t)(k0 + kk) * (2 * HID) + jn0 + c4;
            *(float4*)&Bv[kk][c4] = *(const float4*)bp;
            *(float4*)&Bg[kk][c4] = *(const float4*)(bp + HID);
        }
        __syncthreads();
#pragma unroll
        for (int kk = 0; kk < 16; kk++) {
            float4 a4 = *(const float4*)&As[kk][ty * 4];
            u64t a2[4];
            a2[0] = dup2(a4.x); a2[1] = dup2(a4.y);
            a2[2] = dup2(a4.z); a2[3] = dup2(a4.w);
            // reinterpret consecutive-col float4 smem loads as packed pairs
            ulonglong2 v0 = *(const ulonglong2*)&Bv[kk][tx * 8];
            ulonglong2 v1 = *(const ulonglong2*)&Bv[kk][tx * 8 + 4];
            ulonglong2 g0 = *(const ulonglong2*)&Bg[kk][tx * 8];
            ulonglong2 g1 = *(const ulonglong2*)&Bg[kk][tx * 8 + 4];
#pragma unroll
            for (int i = 0; i < 4; i++) {
                ffma2(accV[i][0], a2[i], v0.x);
                ffma2(accV[i][1], a2[i], v0.y);
                ffma2(accV[i][2], a2[i], v1.x);
                ffma2(accV[i][3], a2[i], v1.y);
                ffma2(accG[i][0], a2[i], g0.x);
                ffma2(accG[i][1], a2[i], g0.y);
                ffma2(accG[i][2], a2[i], g1.x);
                ffma2(accG[i][3], a2[i], g1.y);
            }
        }
        __syncthreads();
    }

    // epilogue: SwiGLU
#pragma unroll
    for (int i = 0; i < 4; i++) {
        int rloc = ty * 4 + i;
        int r = row0 + rloc;
        if (r >= cnt) continue;
        float out[8];
#pragma unroll
        for (int j = 0; j < 4; j++) {
            float v0, v1, g0, g1;
            unpack2(v0, v1, accV[i][j]);
            unpack2(g0, g1, accG[i][j]);
            out[j * 2 + 0] = v0 / (1.f + expf(-g0));
            out[j * 2 + 1] = v1 / (1.f + expf(-g1));
        }
        float* hp = d_he + (size_t)(base + r) * HID + jn0 + tx * 8;
        *(float4*)(hp)     = make_float4(out[0], out[1], out[2], out[3]);
        *(float4*)(hp + 4) = make_float4(out[4], out[5], out[6], out[7]);
    }
}

// ---------------- GEMM2: po[r,:] = gate[r] * (he[r,:] @ w2[e]) ---------------
__global__ void __launch_bounds__(128) gemm2_kernel(const float* __restrict__ w2) {
    int e = blockIdx.z;
    int cnt = d_counts[e];
    int row0 = blockIdx.y * 64;
    if (row0 >= cnt) return;
    int base = d_offsets[e];
    int n0 = blockIdx.x * 64;

    __shared__ float As[16][68];
    __shared__ float Bs[16][64];
    __shared__ float gate_s[64];

    int tid = threadIdx.x;
    if (tid < 64) {
        int rr = row0 + tid;
        gate_s[tid] = (rr < cnt) ? d_row_gate[base + rr] : 0.f;
    }

    const float* w2e = w2 + (size_t)e * HID * DDIM;

    u64t acc[4][4];
#pragma unroll
    for (int i = 0; i < 4; i++)
#pragma unroll
        for (int j = 0; j < 4; j++) acc[i][j] = 0ull;

    int ty = tid >> 3;
    int tx = tid & 7;
    int a_r = tid >> 2;
    int a_c = (tid & 3) << 2;

    for (int k0 = 0; k0 < HID; k0 += 16) {
#pragma unroll
        for (int it = 0; it < 2; it++) {
            int r = a_r + it * 32;
            int rr = row0 + r; if (rr >= cnt) rr = cnt - 1;
            float4 v = *(const float4*)(d_he + (size_t)(base + rr) * HID + k0 + a_c);
            As[a_c + 0][r] = v.x; As[a_c + 1][r] = v.y;
            As[a_c + 2][r] = v.z; As[a_c + 3][r] = v.w;
        }
#pragma unroll
        for (int it = 0; it < 2; it++) {
            int idx = tid + it * 128;
            int kk = idx >> 4;
            int c4 = (idx & 15) << 2;
            *(float4*)&Bs[kk][c4] =
                *(const float4*)(w2e + (size_t)(k0 + kk) * DDIM + n0 + c4);
        }
        __syncthreads();
#pragma unroll
        for (int kk = 0; kk < 16; kk++) {
            float4 a4 = *(const float4*)&As[kk][ty * 4];
            u64t a2[4];
            a2[0] = dup2(a4.x); a2[1] = dup2(a4.y);
            a2[2] = dup2(a4.z); a2[3] = dup2(a4.w);
            ulonglong2 b0 = *(const ulonglong2*)&Bs[kk][tx * 8];
            ulonglong2 b1 = *(const ulonglong2*)&Bs[kk][tx * 8 + 4];
#pragma unroll
            for (int i = 0; i < 4; i++) {
                ffma2(acc[i][0], a2[i], b0.x);
                ffma2(acc[i][1], a2[i], b0.y);
                ffma2(acc[i][2], a2[i], b1.x);
                ffma2(acc[i][3], a2[i], b1.y);
            }
        }
        __syncthreads();
    }

#pragma unroll
    for (int i = 0; i < 4; i++) {
        int rloc = ty * 4 + i;
        int r = row0 + rloc;
        if (r >= cnt) continue;
        float g = gate_s[rloc];
        float o[8];
#pragma unroll
        for (int j = 0; j < 4; j++) {
            float lo, hi;
            unpack2(lo, hi, acc[i][j]);
            o[j * 2 + 0] = g * lo;
            o[j * 2 + 1] = g * hi;
        }
        float* pp = d_po + (size_t)(base + r) * DDIM + n0 + tx * 8;
        *(float4*)(pp)     = make_float4(o[0], o[1], o[2], o[3]);
        *(float4*)(pp + 4) = make_float4(o[4], o[5], o[6], o[7]);
    }
}

// ---------------- combine two expert outputs + unpatchify --------------------
__global__ void combine_kernel(float* __restrict__ y) {
    int idx = blockIdx.x * blockDim.x + threadIdx.x;
    if (idx >= NTOK * DDIM) return;
    int w = idx & 31;
    int h = (idx >> 5) & 31;
    int c = (idx >> 10) & 127;
    int b = idx >> 17;
    int n = (b << 8) + ((h >> 1) << 4) + (w >> 1);
    int d = (c << 2) + ((h & 1) << 1) + (w & 1);
    int pr0 = d_tok_pr[n * 2 + 0];
    int pr1 = d_tok_pr[n * 2 + 1];
    y[idx] = d_po[(size_t)pr0 * DDIM + d] + d_po[(size_t)pr1 * DDIM + d];
}

// ---------------- launch -----------------------------------------------------
extern "C" void kernel_launch(void* const* d_in, const int* in_sizes, int n_in,
                              void* d_out, int out_size) {
    const float* x  = (const float*)d_in[0];
    const float* rw = (const float*)d_in[1];
    const float* w1 = (const float*)d_in[2];
    const float* w2 = (const float*)d_in[3];
    float* y = (float*)d_out;

    reset_kernel<<<1, 32>>>();
    patchify_kernel<<<(NTOK * DDIM + 255) / 256, 256>>>(x);
    router_kernel<<<NTOK / 8, 256>>>(rw);
    offsets_kernel<<<1, 1>>>();
    scatter_kernel<<<(NTOK + 255) / 256, 256>>>();

    dim3 g1(2 * HID / 2 / 64, NTOK / 64, NEXP);   // (16, 64, 8)
    gemm1_kernel<<<g1, 128>>>(w1);
    dim3 g2(DDIM / 64, NTOK / 64, NEXP);          // (8, 64, 8)
    gemm2_kernel<<<g2, 128>>>(w2);

    combine_kernel<<<(NTOK * DDIM + 255) / 256, 256>>>(y);
}

// round 3
// speedup vs baseline: 2.9719x; 2.9494x over previous
#include <cuda_runtime.h>
#include <cuda_bf16.h>
#include <math.h>
#include <stdint.h>

// Problem constants
#define NTOK 4096          // B*(H/2)*(W/2)
#define DDIM 512           // C*p*p
#define NEXP 8
#define HID  1024
#define NPAIR (NTOK * 2)
#define CC   128
#define HH   32
#define WW   32

typedef __nv_bfloat16  bf16;
typedef __nv_bfloat162 bf162;

// ---------------- static device scratch --------------------------------------
__device__ float d_xp [NTOK * DDIM];         // fp32 tokens (router)
__device__ bf16  d_xph[NTOK * DDIM];         // split tokens
__device__ bf16  d_xpl[NTOK * DDIM];
__device__ bf16  d_heh[NPAIR * HID];         // split swiglu activations
__device__ bf16  d_hel[NPAIR * HID];
__device__ float d_po [NPAIR * DDIM];        // gate-scaled expert outputs
__device__ bf16  d_w1h[NEXP * DDIM * 2 * HID];
__device__ bf16  d_w1l[NEXP * DDIM * 2 * HID];
__device__ bf16  d_w2h[NEXP * HID * DDIM];
__device__ bf16  d_w2l[NEXP * HID * DDIM];
__device__ int   d_counts[NEXP];
__device__ int   d_offsets[NEXP];
__device__ int   d_tok_e[NTOK * 2];
__device__ int   d_tok_r[NTOK * 2];
__device__ float d_tok_g[NTOK * 2];
__device__ int   d_tok_pr[NTOK * 2];
__device__ int   d_row_token[NPAIR];
__device__ float d_row_gate[NPAIR];

// ---------------- mma / ldmatrix helpers -------------------------------------
__device__ __forceinline__ uint32_t smem_u32(const void* p) {
    return (uint32_t)__cvta_generic_to_shared(p);
}
__device__ __forceinline__ void ldsm4(uint32_t* r, uint32_t addr) {
    asm volatile("ldmatrix.sync.aligned.m8n8.x4.shared.b16 {%0,%1,%2,%3}, [%4];"
                 : "=r"(r[0]), "=r"(r[1]), "=r"(r[2]), "=r"(r[3]) : "r"(addr));
}
__device__ __forceinline__ void ldsm4t(uint32_t* r, uint32_t addr) {
    asm volatile("ldmatrix.sync.aligned.m8n8.x4.trans.shared.b16 {%0,%1,%2,%3}, [%4];"
                 : "=r"(r[0]), "=r"(r[1]), "=r"(r[2]), "=r"(r[3]) : "r"(addr));
}
__device__ __forceinline__ void mma_bf16(float* d, const uint32_t* a, const uint32_t* b) {
    asm volatile(
        "mma.sync.aligned.m16n8k16.row.col.f32.bf16.bf16.f32 "
        "{%0,%1,%2,%3}, {%4,%5,%6,%7}, {%8,%9}, {%0,%1,%2,%3};"
        : "+f"(d[0]), "+f"(d[1]), "+f"(d[2]), "+f"(d[3])
        : "r"(a[0]), "r"(a[1]), "r"(a[2]), "r"(a[3]), "r"(b[0]), "r"(b[1]));
}
__device__ __forceinline__ void split2(float x, bf16& h, bf16& l) {
    h = __float2bfloat16_rn(x);
    l = __float2bfloat16_rn(x - __bfloat162float(h));
}

// ---------------- reset ------------------------------------------------------
__global__ void reset_kernel() {
    int t = threadIdx.x;
    if (t < NEXP) d_counts[t] = 0;
}

// ---------------- weight split: fp32 -> (hi, lo) bf16 ------------------------
__global__ void convert_w_kernel(const float* __restrict__ w,
                                 bf16* __restrict__ wh, bf16* __restrict__ wl, int n) {
    int i = blockIdx.x * blockDim.x + threadIdx.x;
    int stride = gridDim.x * blockDim.x;
    for (; i < n; i += stride) {
        bf16 h, l; split2(w[i], h, l);
        wh[i] = h; wl[i] = l;
    }
}

// ---------------- patchify: x[B,C,H,W] -> xp[N,d] (fp32 + split) -------------
__global__ void patchify_kernel(const float* __restrict__ x) {
    int idx = blockIdx.x * blockDim.x + threadIdx.x;
    if (idx >= NTOK * DDIM) return;
    int n = idx >> 9;
    int d = idx & 511;
    int b  = n >> 8;
    int h2 = (n >> 4) & 15;
    int w2 = n & 15;
    int c  = d >> 2;
    int ph = (d >> 1) & 1;
    int pw = d & 1;
    float v = x[(((b * CC + c) * HH) + h2 * 2 + ph) * WW + w2 * 2 + pw];
    d_xp[idx] = v;
    bf16 h, l; split2(v, h, l);
    d_xph[idx] = h; d_xpl[idx] = l;
}

// ---------------- router (fp32) ----------------------------------------------
__global__ void router_kernel(const float* __restrict__ rw) {
    __shared__ float rwT[NEXP * DDIM];
    int tid = threadIdx.x;
    for (int i = tid; i < NEXP * DDIM; i += blockDim.x) {
        int k = i >> 3, e = i & 7;
        rwT[e * DDIM + k] = rw[i];
    }
    __syncthreads();

    int warp = tid >> 5, lane = tid & 31;
    int n = blockIdx.x * 8 + warp;
    if (n >= NTOK) return;

    const float* xr = d_xp + (size_t)n * DDIM;
    float acc[NEXP];
#pragma unroll
    for (int e = 0; e < NEXP; e++) acc[e] = 0.f;
#pragma unroll
    for (int t = 0; t < DDIM / 32; t++) {
        int k = lane + t * 32;
        float xv = xr[k];
#pragma unroll
        for (int e = 0; e < NEXP; e++) acc[e] += xv * rwT[e * DDIM + k];
    }
#pragma unroll
    for (int e = 0; e < NEXP; e++) {
#pragma unroll
        for (int off = 16; off > 0; off >>= 1)
            acc[e] += __shfl_xor_sync(0xFFFFFFFFu, acc[e], off);
    }
    if (lane == 0) {
        int i0 = 0; float l0 = acc[0];
#pragma unroll
        for (int e = 1; e < NEXP; e++) if (acc[e] > l0) { l0 = acc[e]; i0 = e; }
        int i1 = -1; float l1 = -1e30f;
#pragma unroll
        for (int e = 0; e < NEXP; e++) if (e != i0 && acc[e] > l1) { l1 = acc[e]; i1 = e; }
        float g0 = 1.f / (1.f + expf(l1 - l0));
        float g1 = 1.f - g0;
        int r0 = atomicAdd(&d_counts[i0], 1);
        int r1 = atomicAdd(&d_counts[i1], 1);
        d_tok_e[n * 2 + 0] = i0; d_tok_r[n * 2 + 0] = r0; d_tok_g[n * 2 + 0] = g0;
        d_tok_e[n * 2 + 1] = i1; d_tok_r[n * 2 + 1] = r1; d_tok_g[n * 2 + 1] = g1;
    }
}

__global__ void offsets_kernel() {
    int s = 0;
    for (int e = 0; e < NEXP; e++) { d_offsets[e] = s; s += d_counts[e]; }
}

__global__ void scatter_kernel() {
    int n = blockIdx.x * blockDim.x + threadIdx.x;
    if (n >= NTOK) return;
#pragma unroll
    for (int j = 0; j < 2; j++) {
        int e = d_tok_e[n * 2 + j];
        int pr = d_offsets[e] + d_tok_r[n * 2 + j];
        d_row_token[pr] = n;
        d_row_gate[pr]  = d_tok_g[n * 2 + j];
        d_tok_pr[n * 2 + j] = pr;
    }
}

// ---------------- GEMM1 (tensor core, 3xBF16 split) + fused SwiGLU -----------
// Block: 64 rows x (64 val cols + 64 gate cols), BK=32, 128 threads (4 warps 2x2)
#define APAD 40            // 32 + 8 halves
#define BPAD 72            // 64 + 8 halves
__global__ void __launch_bounds__(128) gemm1_kernel(int dummy) {
    int e    = blockIdx.z;
    int cnt  = d_counts[e];
    int row0 = blockIdx.y * 64;
    if (row0 >= cnt) return;
    int base = d_offsets[e];
    int jn0  = blockIdx.x * 64;

    __shared__ __align__(16) bf16 Ah[64 * APAD], Al[64 * APAD];
    __shared__ __align__(16) bf16 Bvh[32 * BPAD], Bvl[32 * BPAD];
    __shared__ __align__(16) bf16 Bgh[32 * BPAD], Bgl[32 * BPAD];
    __shared__ int rows_s[64];

    int tid  = threadIdx.x;
    int lane = tid & 31;
    int wid  = tid >> 5;
    int wm   = wid >> 1;        // 0..1 warp row
    int wn   = wid & 1;         // 0..1 warp col
    int lm   = lane & 15;
    int lq   = lane >> 4;

    if (tid < 64) {
        int rr = row0 + tid;
        rows_s[tid] = d_row_token[base + ((rr < cnt) ? rr : (cnt - 1))];
    }
    __syncthreads();

    const bf16* w1h = d_w1h + (size_t)e * DDIM * 2 * HID;
    const bf16* w1l = d_w1l + (size_t)e * DDIM * 2 * HID;

    float accV[2][4][4], accG[2][4][4];
#pragma unroll
    for (int a = 0; a < 2; a++)
#pragma unroll
        for (int b = 0; b < 4; b++)
#pragma unroll
            for (int c = 0; c < 4; c++) { accV[a][b][c] = 0.f; accG[a][b][c] = 0.f; }

    // global-load thread mapping
    int ar = tid >> 2, ac = (tid & 3) * 8;      // A: 32 rows/pass, 8 halves
    int br = tid >> 3, bc = (tid & 7) * 8;      // B: 16 rows/pass, 8 halves

    for (int k0 = 0; k0 < DDIM; k0 += 32) {
#pragma unroll
        for (int p = 0; p < 2; p++) {
            int r = ar + p * 32;
            const bf16* sh = d_xph + (size_t)rows_s[r] * DDIM + k0 + ac;
            const bf16* sl = d_xpl + (size_t)rows_s[r] * DDIM + k0 + ac;
            *(uint4*)&Ah[r * APAD + ac] = *(const uint4*)sh;
            *(uint4*)&Al[r * APAD + ac] = *(const uint4*)sl;
        }
#pragma unroll
        for (int p = 0; p < 2; p++) {
            int r = br + p * 16;
            size_t go = (size_t)(k0 + r) * (2 * HID) + jn0 + bc;
            *(uint4*)&Bvh[r * BPAD + bc] = *(const uint4*)(w1h + go);
            *(uint4*)&Bvl[r * BPAD + bc] = *(const uint4*)(w1l + go);
            *(uint4*)&Bgh[r * BPAD + bc] = *(const uint4*)(w1h + go + HID);
            *(uint4*)&Bgl[r * BPAD + bc] = *(const uint4*)(w1l + go + HID);
        }
        __syncthreads();

#pragma unroll
        for (int s = 0; s < 2; s++) {
            uint32_t ah[2][4], al[2][4];
#pragma unroll
            for (int tm = 0; tm < 2; tm++) {
                uint32_t ao = smem_u32(&Ah[(wm * 32 + tm * 16 + lm) * APAD + s * 16 + lq * 8]);
                ldsm4(ah[tm], ao);
                uint32_t ao2 = smem_u32(&Al[(wm * 32 + tm * 16 + lm) * APAD + s * 16 + lq * 8]);
                ldsm4(al[tm], ao2);
            }
            uint32_t bvh[2][4], bvl[2][4], bgh[2][4], bgl[2][4];
#pragma unroll
            for (int nt = 0; nt < 2; nt++) {
                uint32_t bo = (s * 16 + lm) * BPAD + wn * 32 + nt * 16 + lq * 8;
                ldsm4t(bvh[nt], smem_u32(&Bvh[bo]));
                ldsm4t(bvl[nt], smem_u32(&Bvl[bo]));
                ldsm4t(bgh[nt], smem_u32(&Bgh[bo]));
                ldsm4t(bgl[nt], smem_u32(&Bgl[bo]));
            }
#pragma unroll
            for (int tm = 0; tm < 2; tm++) {
#pragma unroll
                for (int j = 0; j < 4; j++) {
                    int nt = j >> 1, o = (j & 1) * 2;
                    mma_bf16(accV[tm][j], ah[tm], &bvh[nt][o]);
                    mma_bf16(accV[tm][j], ah[tm], &bvl[nt][o]);
                    mma_bf16(accV[tm][j], al[tm], &bvh[nt][o]);
                    mma_bf16(accG[tm][j], ah[tm], &bgh[nt][o]);
                    mma_bf16(accG[tm][j], ah[tm], &bgl[nt][o]);
                    mma_bf16(accG[tm][j], al[tm], &bgh[nt][o]);
                }
            }
        }
        __syncthreads();
    }

    // epilogue: SwiGLU, write split bf16 he
    int qr = lane >> 2, qc = lane & 3;
#pragma unroll
    for (int tm = 0; tm < 2; tm++) {
#pragma unroll
        for (int p = 0; p < 2; p++) {
            int rl = wm * 32 + tm * 16 + qr + p * 8;
            int r  = row0 + rl;
            if (r >= cnt) continue;
            size_t rowoff = (size_t)(base + r) * HID;
#pragma unroll
            for (int j = 0; j < 4; j++) {
                float v0 = accV[tm][j][p * 2], v1 = accV[tm][j][p * 2 + 1];
                float g0 = accG[tm][j][p * 2], g1 = accG[tm][j][p * 2 + 1];
                float o0 = v0 / (1.f + expf(-g0));
                float o1 = v1 / (1.f + expf(-g1));
                bf16 h0, l0, h1, l1;
                split2(o0, h0, l0); split2(o1, h1, l1);
                int col = jn0 + wn * 32 + j * 8 + qc * 2;
                *(bf162*)&d_heh[rowoff + col] = bf162(h0, h1);
                *(bf162*)&d_hel[rowoff + col] = bf162(l0, l1);
            }
        }
    }
}

// ---------------- GEMM2 (tensor core, 3xBF16 split), gate-scaled -------------
__global__ void __launch_bounds__(128) gemm2_kernel(int dummy) {
    int e    = blockIdx.z;
    int cnt  = d_counts[e];
    int row0 = blockIdx.y * 64;
    if (row0 >= cnt) return;
    int base = d_offsets[e];
    int n0   = blockIdx.x * 64;

    __shared__ __align__(16) bf16 Ah[64 * APAD], Al[64 * APAD];
    __shared__ __align__(16) bf16 Bh[32 * BPAD], Bl[32 * BPAD];
    __shared__ float gate_s[64];

    int tid  = threadIdx.x;
    int lane = tid & 31;
    int wid  = tid >> 5;
    int wm   = wid >> 1;
    int wn   = wid & 1;
    int lm   = lane & 15;
    int lq   = lane >> 4;

    if (tid < 64) {
        int rr = row0 + tid;
        gate_s[tid] = (rr < cnt) ? d_row_gate[base + rr] : 0.f;
    }
    __syncthreads();

    const bf16* w2h = d_w2h + (size_t)e * HID * DDIM;
    const bf16* w2l = d_w2l + (size_t)e * HID * DDIM;

    float acc[2][4][4];
#pragma unroll
    for (int a = 0; a < 2; a++)
#pragma unroll
        for (int b = 0; b < 4; b++)
#pragma unroll
            for (int c = 0; c < 4; c++) acc[a][b][c] = 0.f;

    int ar = tid >> 2, ac = (tid & 3) * 8;
    int br = tid >> 3, bc = (tid & 7) * 8;

    for (int k0 = 0; k0 < HID; k0 += 32) {
#pragma unroll
        for (int p = 0; p < 2; p++) {
            int r = ar + p * 32;
            int rr = row0 + r; if (rr >= cnt) rr = cnt - 1;
            size_t rowoff = (size_t)(base + rr) * HID + k0 + ac;
            *(uint4*)&Ah[r * APAD + ac] = *(const uint4*)(d_heh + rowoff);
            *(uint4*)&Al[r * APAD + ac] = *(const uint4*)(d_hel + rowoff);
        }
#pragma unroll
        for (int p = 0; p < 2; p++) {
            int r = br + p * 16;
            size_t go = (size_t)(k0 + r) * DDIM + n0 + bc;
            *(uint4*)&Bh[r * BPAD + bc] = *(const uint4*)(w2h + go);
            *(uint4*)&Bl[r * BPAD + bc] = *(const uint4*)(w2l + go);
        }
        __syncthreads();

#pragma unroll
        for (int s = 0; s < 2; s++) {
            uint32_t ah[2][4], al[2][4];
#pragma unroll
            for (int tm = 0; tm < 2; tm++) {
                uint32_t off = (wm * 32 + tm * 16 + lm) * APAD + s * 16 + lq * 8;
                ldsm4(ah[tm], smem_u32(&Ah[off]));
                ldsm4(al[tm], smem_u32(&Al[off]));
            }
            uint32_t bh[2][4], bl[2][4];
#pragma unroll
            for (int nt = 0; nt < 2; nt++) {
                uint32_t bo = (s * 16 + lm) * BPAD + wn * 32 + nt * 16 + lq * 8;
                ldsm4t(bh[nt], smem_u32(&Bh[bo]));
                ldsm4t(bl[nt], smem_u32(&Bl[bo]));
            }
#pragma unroll
            for (int tm = 0; tm < 2; tm++) {
#pragma unroll
                for (int j = 0; j < 4; j++) {
                    int nt = j >> 1, o = (j & 1) * 2;
                    mma_bf16(acc[tm][j], ah[tm], &bh[nt][o]);
                    mma_bf16(acc[tm][j], ah[tm], &bl[nt][o]);
                    mma_bf16(acc[tm][j], al[tm], &bh[nt][o]);
                }
            }
        }
        __syncthreads();
    }

    int qr = lane >> 2, qc = lane & 3;
#pragma unroll
    for (int tm = 0; tm < 2; tm++) {
#pragma unroll
        for (int p = 0; p < 2; p++) {
            int rl = wm * 32 + tm * 16 + qr + p * 8;
            int r  = row0 + rl;
            if (r >= cnt) continue;
            float g = gate_s[rl];
            size_t rowoff = (size_t)(base + r) * DDIM;
#pragma unroll
            for (int j = 0; j < 4; j++) {
                int col = n0 + wn * 32 + j * 8 + qc * 2;
                float2 o = make_float2(g * acc[tm][j][p * 2], g * acc[tm][j][p * 2 + 1]);
                *(float2*)&d_po[rowoff + col] = o;
            }
        }
    }
}

// ---------------- combine two expert outputs + unpatchify --------------------
__global__ void combine_kernel(float* __restrict__ y) {
    int idx = blockIdx.x * blockDim.x + threadIdx.x;
    if (idx >= NTOK * DDIM) return;
    int w = idx & 31;
    int h = (idx >> 5) & 31;
    int c = (idx >> 10) & 127;
    int b = idx >> 17;
    int n = (b << 8) + ((h >> 1) << 4) + (w >> 1);
    int d = (c << 2) + ((h & 1) << 1) + (w & 1);
    int pr0 = d_tok_pr[n * 2 + 0];
    int pr1 = d_tok_pr[n * 2 + 1];
    y[idx] = d_po[(size_t)pr0 * DDIM + d] + d_po[(size_t)pr1 * DDIM + d];
}

// ---------------- launch -----------------------------------------------------
extern "C" void kernel_launch(void* const* d_in, const int* in_sizes, int n_in,
                              void* d_out, int out_size) {
    const float* x  = (const float*)d_in[0];
    const float* rw = (const float*)d_in[1];
    const float* w1 = (const float*)d_in[2];
    const float* w2 = (const float*)d_in[3];
    float* y = (float*)d_out;

    reset_kernel<<<1, 32>>>();

    bf16 *w1h, *w1l, *w2h, *w2l;
    cudaGetSymbolAddress((void**)&w1h, d_w1h);
    cudaGetSymbolAddress((void**)&w1l, d_w1l);
    cudaGetSymbolAddress((void**)&w2h, d_w2h);
    cudaGetSymbolAddress((void**)&w2l, d_w2l);
    convert_w_kernel<<<1024, 256>>>(w1, w1h, w1l, NEXP * DDIM * 2 * HID);
    convert_w_kernel<<<1024, 256>>>(w2, w2h, w2l, NEXP * HID * DDIM);

    patchify_kernel<<<(NTOK * DDIM + 255) / 256, 256>>>(x);
    router_kernel<<<NTOK / 8, 256>>>(rw);
    offsets_kernel<<<1, 1>>>();
    scatter_kernel<<<(NTOK + 255) / 256, 256>>>();

    dim3 g1(HID / 64, NTOK / 64, NEXP);       // (16, 64, 8)
    gemm1_kernel<<<g1, 128>>>(0);
    dim3 g2(DDIM / 64, NTOK / 64, NEXP);      // (8, 64, 8)
    gemm2_kernel<<<g2, 128>>>(0);

    combine_kernel<<<(NTOK * DDIM + 255) / 256, 256>>>(y);
}

// round 5
// speedup vs baseline: 2.9887x; 1.0056x over previous
#include <cuda_runtime.h>
#include <cuda_bf16.h>
#include <math.h>
#include <stdint.h>

// Problem constants
#define NTOK 4096
#define DDIM 512
#define NEXP 8
#define HID  1024
#define NPAIR (NTOK * 2)
#define CC   128
#define HH   32
#define WW   32

typedef __nv_bfloat16  bf16;
typedef __nv_bfloat162 bf162;

// ---------------- static device scratch --------------------------------------
__device__ float d_xp [NTOK * DDIM];
__device__ __align__(256) bf16 d_xph[NTOK * DDIM];
__device__ __align__(256) bf16 d_xpl[NTOK * DDIM];
__device__ __align__(256) bf16 d_heh[NPAIR * HID];
__device__ __align__(256) bf16 d_hel[NPAIR * HID];
__device__ float d_po [NPAIR * DDIM];
__device__ __align__(256) bf16 d_w1h[NEXP * DDIM * 2 * HID];
__device__ __align__(256) bf16 d_w1l[NEXP * DDIM * 2 * HID];
__device__ __align__(256) bf16 d_w2h[NEXP * HID * DDIM];
__device__ __align__(256) bf16 d_w2l[NEXP * HID * DDIM];
__device__ int   d_counts[NEXP];
__device__ int   d_offsets[NEXP];
__device__ int   d_tok_e[NTOK * 2];
__device__ int   d_tok_r[NTOK * 2];
__device__ float d_tok_g[NTOK * 2];
__device__ int   d_tok_pr[NTOK * 2];
__device__ int   d_row_token[NPAIR];
__device__ float d_row_gate[NPAIR];

// ---------------- helpers -----------------------------------------------------
__device__ __forceinline__ uint32_t smem_u32(const void* p) {
    return (uint32_t)__cvta_generic_to_shared(p);
}
__device__ __forceinline__ void ldsm4(uint32_t* r, uint32_t addr) {
    asm volatile("ldmatrix.sync.aligned.m8n8.x4.shared.b16 {%0,%1,%2,%3}, [%4];"
                 : "=r"(r[0]), "=r"(r[1]), "=r"(r[2]), "=r"(r[3]) : "r"(addr));
}
__device__ __forceinline__ void ldsm4t(uint32_t* r, uint32_t addr) {
    asm volatile("ldmatrix.sync.aligned.m8n8.x4.trans.shared.b16 {%0,%1,%2,%3}, [%4];"
                 : "=r"(r[0]), "=r"(r[1]), "=r"(r[2]), "=r"(r[3]) : "r"(addr));
}
__device__ __forceinline__ void mma_bf16(float* d, const uint32_t* a, const uint32_t* b) {
    asm volatile(
        "mma.sync.aligned.m16n8k16.row.col.f32.bf16.bf16.f32 "
        "{%0,%1,%2,%3}, {%4,%5,%6,%7}, {%8,%9}, {%0,%1,%2,%3};"
        : "+f"(d[0]), "+f"(d[1]), "+f"(d[2]), "+f"(d[3])
        : "r"(a[0]), "r"(a[1]), "r"(a[2]), "r"(a[3]), "r"(b[0]), "r"(b[1]));
}
__device__ __forceinline__ void split2(float x, bf16& h, bf16& l) {
    h = __float2bfloat16_rn(x);
    l = __float2bfloat16_rn(x - __bfloat162float(h));
}
__device__ __forceinline__ void cpa16(uint32_t dst, const void* src) {
    asm volatile("cp.async.cg.shared.global [%0], [%1], 16;" :: "r"(dst), "l"(src));
}
__device__ __forceinline__ void cpa_commit() {
    asm volatile("cp.async.commit_group;" ::: "memory");
}
template<int N> __device__ __forceinline__ void cpa_wait() {
    asm volatile("cp.async.wait_group %0;" :: "n"(N) : "memory");
}

// Tile geometry
#define BM   128
#define BK   32
#define APAD 40     // 32 + 8 halves (80B rows, 16B-aligned)
#define BPAD 72     // 64 + 8 halves (144B rows, 16B-aligned)
#define A_ELE (BM * APAD)         // 5120
#define B_ELE (BK * BPAD)         // 2304

// ---------------- convert + reset (launch 0 and 1) ---------------------------
__global__ void convert_w_kernel(const float* __restrict__ w,
                                 bf16* __restrict__ wh, bf16* __restrict__ wl,
                                 int n, int do_reset) {
    int i = blockIdx.x * blockDim.x + threadIdx.x;
    if (do_reset && blockIdx.x == 0 && threadIdx.x < NEXP) d_counts[threadIdx.x] = 0;
    int stride = gridDim.x * blockDim.x;
    for (; i < n; i += stride) {
        bf16 h, l; split2(w[i], h, l);
        wh[i] = h; wl[i] = l;
    }
}

// ---------------- patchify (launch 2) ----------------------------------------
__global__ void patchify_kernel(const float* __restrict__ x) {
    int idx = blockIdx.x * blockDim.x + threadIdx.x;
    if (idx >= NTOK * DDIM) return;
    int n = idx >> 9;
    int d = idx & 511;
    int b  = n >> 8;
    int h2 = (n >> 4) & 15;
    int w2 = n & 15;
    int c  = d >> 2;
    int ph = (d >> 1) & 1;
    int pw = d & 1;
    float v = x[(((b * CC + c) * HH) + h2 * 2 + ph) * WW + w2 * 2 + pw];
    d_xp[idx] = v;
    bf16 h, l; split2(v, h, l);
    d_xph[idx] = h; d_xpl[idx] = l;
}

// ---------------- router (launch 3) ------------------------------------------
__global__ void router_kernel(const float* __restrict__ rw) {
    __shared__ float rwT[NEXP * DDIM];
    int tid = threadIdx.x;
    for (int i = tid; i < NEXP * DDIM; i += blockDim.x) {
        int k = i >> 3, e = i & 7;
        rwT[e * DDIM + k] = rw[i];
    }
    __syncthreads();

    int warp = tid >> 5, lane = tid & 31;
    int n = blockIdx.x * 8 + warp;
    if (n >= NTOK) return;

    const float* xr = d_xp + (size_t)n * DDIM;
    float acc[NEXP];
#pragma unroll
    for (int e = 0; e < NEXP; e++) acc[e] = 0.f;
#pragma unroll
    for (int t = 0; t < DDIM / 32; t++) {
        int k = lane + t * 32;
        float xv = xr[k];
#pragma unroll
        for (int e = 0; e < NEXP; e++) acc[e] += xv * rwT[e * DDIM + k];
    }
#pragma unroll
    for (int e = 0; e < NEXP; e++) {
#pragma unroll
        for (int off = 16; off > 0; off >>= 1)
            acc[e] += __shfl_xor_sync(0xFFFFFFFFu, acc[e], off);
    }
    if (lane == 0) {
        int i0 = 0; float l0 = acc[0];
#pragma unroll
        for (int e = 1; e < NEXP; e++) if (acc[e] > l0) { l0 = acc[e]; i0 = e; }
        int i1 = -1; float l1 = -1e30f;
#pragma unroll
        for (int e = 0; e < NEXP; e++) if (e != i0 && acc[e] > l1) { l1 = acc[e]; i1 = e; }
        float g0 = 1.f / (1.f + expf(l1 - l0));
        float g1 = 1.f - g0;
        int r0 = atomicAdd(&d_counts[i0], 1);
        int r1 = atomicAdd(&d_counts[i1], 1);
        d_tok_e[n * 2 + 0] = i0; d_tok_r[n * 2 + 0] = r0; d_tok_g[n * 2 + 0] = g0;
        d_tok_e[n * 2 + 1] = i1; d_tok_r[n * 2 + 1] = r1; d_tok_g[n * 2 + 1] = g1;
    }
}

// ---------------- scatter + offsets in one single-block kernel (launch 4) ----
__global__ void scatter_kernel() {
    __shared__ int off_s[NEXP];
    int tid = threadIdx.x;
    if (tid == 0) {
        int s = 0;
        for (int e = 0; e < NEXP; e++) { off_s[e] = s; d_offsets[e] = s; s += d_counts[e]; }
    }
    __syncthreads();
    for (int n = tid; n < NTOK; n += blockDim.x) {
#pragma unroll
        for (int j = 0; j < 2; j++) {
            int e = d_tok_e[n * 2 + j];
            int pr = off_s[e] + d_tok_r[n * 2 + j];
            d_row_token[pr] = n;
            d_row_gate[pr]  = d_tok_g[n * 2 + j];
            d_tok_pr[n * 2 + j] = pr;
        }
    }
}

// ---------------- GEMM1 (launch 5): 128x(64v+64g) tiles, 2-stage pipeline ----
#define G1_STG (2 * A_ELE + 4 * B_ELE)     // bf16 elems per stage = 19456
#define G1_SMEM (2 * G1_STG * 2)           // bytes = 77824
__global__ void __launch_bounds__(256) gemm1_kernel() {
    extern __shared__ bf16 S[];
    __shared__ int rows_s[BM];

    int e    = blockIdx.z;
    int cnt  = d_counts[e];
    int row0 = blockIdx.y * BM;
    if (row0 >= cnt) return;
    int base = d_offsets[e];
    int jn0  = blockIdx.x * 64;

    int tid  = threadIdx.x;
    int lane = tid & 31;
    int wid  = tid >> 5;
    int wm   = wid >> 1;          // 0..3
    int wn   = wid & 1;           // 0..1
    int lm   = lane & 15;
    int lq   = lane >> 4;

    if (tid < BM) {
        int rr = row0 + tid;
        rows_s[tid] = d_row_token[base + ((rr < cnt) ? rr : (cnt - 1))];
    }
    __syncthreads();

    const bf16* w1h = d_w1h + (size_t)e * DDIM * 2 * HID;
    const bf16* w1l = d_w1l + (size_t)e * DDIM * 2 * HID;

    float accV[2][4][4], accG[2][4][4];
#pragma unroll
    for (int a = 0; a < 2; a++)
#pragma unroll
        for (int b = 0; b < 4; b++)
#pragma unroll
            for (int c = 0; c < 4; c++) { accV[a][b][c] = 0.f; accG[a][b][c] = 0.f; }

    // load mappings
    int a_id0 = tid * 2;                       // 2 A-chunks per thread
    int b_r = tid >> 3, b_c = (tid & 7) * 8;   // 1 chunk per B array

#define G1_LOAD(st, k0)                                                          \
    {                                                                            \
        bf16* Ah = S + (st) * G1_STG;                                            \
        bf16* Al = Ah + A_ELE;                                                   \
        bf16* Bvh = Al + A_ELE;                                                  \
        bf16* Bvl = Bvh + B_ELE;                                                 \
        bf16* Bgh = Bvl + B_ELE;                                                 \
        bf16* Bgl = Bgh + B_ELE;                                                 \
        _Pragma("unroll")                                                        \
        for (int i = 0; i < 2; i++) {                                            \
            int id = a_id0 + i;                                                  \
            int r = id >> 2, c = (id & 3) * 8;                                   \
            size_t go = (size_t)rows_s[r] * DDIM + (k0) + c;                     \
            cpa16(smem_u32(Ah + r * APAD + c), d_xph + go);                      \
            cpa16(smem_u32(Al + r * APAD + c), d_xpl + go);                      \
        }                                                                        \
        size_t gv = (size_t)((k0) + b_r) * (2 * HID) + jn0 + b_c;                \
        cpa16(smem_u32(Bvh + b_r * BPAD + b_c), w1h + gv);                       \
        cpa16(smem_u32(Bvl + b_r * BPAD + b_c), w1l + gv);                       \
        cpa16(smem_u32(Bgh + b_r * BPAD + b_c), w1h + gv + HID);                 \
        cpa16(smem_u32(Bgl + b_r * BPAD + b_c), w1l + gv + HID);                 \
    }

    G1_LOAD(0, 0);
    cpa_commit();

    for (int ch = 0; ch < DDIM / BK; ch++) {
        if (ch + 1 < DDIM / BK) {
            G1_LOAD((ch + 1) & 1, (ch + 1) * BK);
            cpa_commit();
            cpa_wait<1>();
        } else {
            cpa_wait<0>();
        }
        __syncthreads();

        bf16* Ah = S + (ch & 1) * G1_STG;
        bf16* Al = Ah + A_ELE;
        bf16* Bvh = Al + A_ELE;
        bf16* Bvl = Bvh + B_ELE;
        bf16* Bgh = Bvl + B_ELE;
        bf16* Bgl = Bgh + B_ELE;

#pragma unroll
        for (int s = 0; s < 2; s++) {
            uint32_t ah[2][4], al[2][4];
#pragma unroll
            for (int tm = 0; tm < 2; tm++) {
                int ro = (wm * 32 + tm * 16 + lm) * APAD + s * 16 + lq * 8;
                ldsm4(ah[tm], smem_u32(Ah + ro));
                ldsm4(al[tm], smem_u32(Al + ro));
            }
            uint32_t bvh[2][4], bvl[2][4], bgh[2][4], bgl[2][4];
#pragma unroll
            for (int nt = 0; nt < 2; nt++) {
                int bo = (s * 16 + lm) * BPAD + wn * 32 + nt * 16 + lq * 8;
                ldsm4t(bvh[nt], smem_u32(Bvh + bo));
                ldsm4t(bvl[nt], smem_u32(Bvl + bo));
                ldsm4t(bgh[nt], smem_u32(Bgh + bo));
                ldsm4t(bgl[nt], smem_u32(Bgl + bo));
            }
#pragma unroll
            for (int tm = 0; tm < 2; tm++) {
#pragma unroll
                for (int j = 0; j < 4; j++) {
                    int nt = j >> 1, o = (j & 1) * 2;
                    mma_bf16(accV[tm][j], ah[tm], &bvh[nt][o]);
                    mma_bf16(accV[tm][j], ah[tm], &bvl[nt][o]);
                    mma_bf16(accV[tm][j], al[tm], &bvh[nt][o]);
                    mma_bf16(accG[tm][j], ah[tm], &bgh[nt][o]);
                    mma_bf16(accG[tm][j], ah[tm], &bgl[nt][o]);
                    mma_bf16(accG[tm][j], al[tm], &bgh[nt][o]);
                }
            }
        }
        __syncthreads();
    }

    // epilogue: SwiGLU, split-bf16 store of he
    int qr = lane >> 2, qc = lane & 3;
#pragma unroll
    for (int tm = 0; tm < 2; tm++) {
#pragma unroll
        for (int p = 0; p < 2; p++) {
            int rl = wm * 32 + tm * 16 + qr + p * 8;
            int r  = row0 + rl;
            if (r >= cnt) continue;
            size_t ho = (size_t)(base + r) * HID;
#pragma unroll
            for (int j = 0; j < 4; j++) {
                float v0 = accV[tm][j][p * 2], v1 = accV[tm][j][p * 2 + 1];
                float g0 = accG[tm][j][p * 2], g1 = accG[tm][j][p * 2 + 1];
                float o0 = v0 / (1.f + expf(-g0));
                float o1 = v1 / (1.f + expf(-g1));
                bf16 h0, l0, h1, l1;
                split2(o0, h0, l0); split2(o1, h1, l1);
                int col = jn0 + wn * 32 + j * 8 + qc * 2;
                *(bf162*)&d_heh[ho + col] = bf162(h0, h1);
                *(bf162*)&d_hel[ho + col] = bf162(l0, l1);
            }
        }
    }
}

// ---------------- GEMM2 (launch 6): 128x64 tiles, 2-stage pipeline -----------
#define G2_STG (2 * A_ELE + 2 * B_ELE)     // 14848 elems
#define G2_SMEM (2 * G2_STG * 2)           // 59392 B
__global__ void __launch_bounds__(256) gemm2_kernel() {
    extern __shared__ bf16 S[];
    __shared__ float gate_s[BM];

    int e    = blockIdx.z;
    int cnt  = d_counts[e];
    int row0 = blockIdx.y * BM;
    if (row0 >= cnt) return;
    int base = d_offsets[e];
    int n0   = blockIdx.x * 64;

    int tid  = threadIdx.x;
    int lane = tid & 31;
    int wid  = tid >> 5;
    int wm   = wid >> 1;
    int wn   = wid & 1;
    int lm   = lane & 15;
    int lq   = lane >> 4;

    if (tid < BM) {
        int rr = row0 + tid;
        gate_s[tid] = (rr < cnt) ? d_row_gate[base + rr] : 0.f;
    }
    __syncthreads();

    const bf16* w2h = d_w2h + (size_t)e * HID * DDIM;
    const bf16* w2l = d_w2l + (size_t)e * HID * DDIM;

    float acc[2][4][4];
#pragma unroll
    for (int a = 0; a < 2; a++)
#pragma unroll
        for (int b = 0; b < 4; b++)
#pragma unroll
            for (int c = 0; c < 4; c++) acc[a][b][c] = 0.f;

    int a_id0 = tid * 2;
    int b_r = tid >> 3, b_c = (tid & 7) * 8;

#define G2_LOAD(st, k0)                                                          \
    {                                                                            \
        bf16* Ah = S + (st) * G2_STG;                                            \
        bf16* Al = Ah + A_ELE;                                                   \
        bf16* Bh = Al + A_ELE;                                                   \
        bf16* Bl = Bh + B_ELE;                                                   \
        _Pragma("unroll")                                                        \
        for (int i = 0; i < 2; i++) {                                            \
            int id = a_id0 + i;                                                  \
            int r = id >> 2, c = (id & 3) * 8;                                   \
            int rr = row0 + r; if (rr >= cnt) rr = cnt - 1;                      \
            size_t go = (size_t)(base + rr) * HID + (k0) + c;                    \
            cpa16(smem_u32(Ah + r * APAD + c), d_heh + go);                      \
            cpa16(smem_u32(Al + r * APAD + c), d_hel + go);                      \
        }                                                                        \
        size_t gb = (size_t)((k0) + b_r) * DDIM + n0 + b_c;                      \
        cpa16(smem_u32(Bh + b_r * BPAD + b_c), w2h + gb);                        \
        cpa16(smem_u32(Bl + b_r * BPAD + b_c), w2l + gb);                        \
    }

    G2_LOAD(0, 0);
    cpa_commit();

    for (int ch = 0; ch < HID / BK; ch++) {
        if (ch + 1 < HID / BK) {
            G2_LOAD((ch + 1) & 1, (ch + 1) * BK);
            cpa_commit();
            cpa_wait<1>();
        } else {
            cpa_wait<0>();
        }
        __syncthreads();

        bf16* Ah = S + (ch & 1) * G2_STG;
        bf16* Al = Ah + A_ELE;
        bf16* Bh = Al + A_ELE;
        bf16* Bl = Bh + B_ELE;

#pragma unroll
        for (int s = 0; s < 2; s++) {
            uint32_t ah[2][4], al[2][4];
#pragma unroll
            for (int tm = 0; tm < 2; tm++) {
                int ro = (wm * 32 + tm * 16 + lm) * APAD + s * 16 + lq * 8;
                ldsm4(ah[tm], smem_u32(Ah + ro));
                ldsm4(al[tm], smem_u32(Al + ro));
            }
            uint32_t bh[2][4], bl[2][4];
#pragma unroll
            for (int nt = 0; nt < 2; nt++) {
                int bo = (s * 16 + lm) * BPAD + wn * 32 + nt * 16 + lq * 8;
                ldsm4t(bh[nt], smem_u32(Bh + bo));
                ldsm4t(bl[nt], smem_u32(Bl + bo));
            }
#pragma unroll
            for (int tm = 0; tm < 2; tm++) {
#pragma unroll
                for (int j = 0; j < 4; j++) {
                    int nt = j >> 1, o = (j & 1) * 2;
                    mma_bf16(acc[tm][j], ah[tm], &bh[nt][o]);
                    mma_bf16(acc[tm][j], ah[tm], &bl[nt][o]);
                    mma_bf16(acc[tm][j], al[tm], &bh[nt][o]);
                }
            }
        }
        __syncthreads();
    }

    int qr = lane >> 2, qc = lane & 3;
#pragma unroll
    for (int tm = 0; tm < 2; tm++) {
#pragma unroll
        for (int p = 0; p < 2; p++) {
            int rl = wm * 32 + tm * 16 + qr + p * 8;
            int r  = row0 + rl;
            if (r >= cnt) continue;
            float g = gate_s[rl];
            size_t po = (size_t)(base + r) * DDIM;
#pragma unroll
            for (int j = 0; j < 4; j++) {
                int col = n0 + wn * 32 + j * 8 + qc * 2;
                float2 o = make_float2(g * acc[tm][j][p * 2], g * acc[tm][j][p * 2 + 1]);
                *(float2*)&d_po[po + col] = o;
            }
        }
    }
}

// ---------------- combine (launch 7) -----------------------------------------
__global__ void combine_kernel(float* __restrict__ y) {
    int idx = blockIdx.x * blockDim.x + threadIdx.x;
    if (idx >= NTOK * DDIM) return;
    int w = idx & 31;
    int h = (idx >> 5) & 31;
    int c = (idx >> 10) & 127;
    int b = idx >> 17;
    int n = (b << 8) + ((h >> 1) << 4) + (w >> 1);
    int d = (c << 2) + ((h & 1) << 1) + (w & 1);
    int pr0 = d_tok_pr[n * 2 + 0];
    int pr1 = d_tok_pr[n * 2 + 1];
    y[idx] = d_po[(size_t)pr0 * DDIM + d] + d_po[(size_t)pr1 * DDIM + d];
}

// ---------------- launch -----------------------------------------------------
extern "C" void kernel_launch(void* const* d_in, const int* in_sizes, int n_in,
                              void* d_out, int out_size) {
    const float* x  = (const float*)d_in[0];
    const float* rw = (const float*)d_in[1];
    const float* w1 = (const float*)d_in[2];
    const float* w2 = (const float*)d_in[3];
    float* y = (float*)d_out;

    cudaFuncSetAttribute(gemm1_kernel, cudaFuncAttributeMaxDynamicSharedMemorySize, G1_SMEM);
    cudaFuncSetAttribute(gemm2_kernel, cudaFuncAttributeMaxDynamicSharedMemorySize, G2_SMEM);

    bf16 *w1h, *w1l, *w2h, *w2l;
    cudaGetSymbolAddress((void**)&w1h, d_w1h);
    cudaGetSymbolAddress((void**)&w1l, d_w1l);
    cudaGetSymbolAddress((void**)&w2h, d_w2h);
    cudaGetSymbolAddress((void**)&w2l, d_w2l);

    convert_w_kernel<<<1024, 256>>>(w1, w1h, w1l, NEXP * DDIM * 2 * HID, 1);  // 0 (+reset)
    convert_w_kernel<<<1024, 256>>>(w2, w2h, w2l, NEXP * HID * DDIM, 0);      // 1
    patchify_kernel<<<(NTOK * DDIM + 255) / 256, 256>>>(x);                   // 2
    router_kernel<<<NTOK / 8, 256>>>(rw);                                     // 3
    scatter_kernel<<<1, 256>>>();                                             // 4
    gemm1_kernel<<<dim3(HID / 64, NTOK / BM, NEXP), 256, G1_SMEM>>>();        // 5 (ncu -s5)
    gemm2_kernel<<<dim3(DDIM / 64, NTOK / BM, NEXP), 256, G2_SMEM>>>();       // 6
    combine_kernel<<<(NTOK * DDIM + 255) / 256, 256>>>(y);                    // 7
}

// round 6
// speedup vs baseline: 3.9176x; 1.3108x over previous
#include <cuda_runtime.h>
#include <cuda_fp16.h>
#include <math.h>
#include <stdint.h>

// Problem constants
#define NTOK 4096
#define DDIM 512
#define NEXP 8
#define HID  1024
#define NPAIR (NTOK * 2)
#define CC   128
#define HH   32
#define WW   32

typedef __half  f16;
typedef __half2 f162;

// ---------------- static device scratch --------------------------------------
__device__ float d_xp [NTOK * DDIM];                     // fp32 tokens (router)
__device__ __align__(256) f16 d_xph[NTOK * DDIM];        // fp16 tokens (GEMM1 A)
__device__ __align__(256) f16 d_heh[NPAIR * HID];        // fp16 swiglu acts (GEMM2 A)
__device__ float d_po [NPAIR * DDIM];                    // gate-scaled outputs
__device__ __align__(256) f16 d_w1h[NEXP * DDIM * 2 * HID];  // w1 split hi
__device__ __align__(256) f16 d_w1l[NEXP * DDIM * 2 * HID];  // w1 split lo
__device__ __align__(256) f16 d_w2h[NEXP * HID * DDIM];
__device__ __align__(256) f16 d_w2l[NEXP * HID * DDIM];
__device__ int   d_counts[NEXP];
__device__ int   d_offsets[NEXP];
__device__ int   d_tok_e[NTOK * 2];
__device__ int   d_tok_r[NTOK * 2];
__device__ float d_tok_g[NTOK * 2];
__device__ int   d_tok_pr[NTOK * 2];
__device__ int   d_row_token[NPAIR];
__device__ float d_row_gate[NPAIR];

// ---------------- helpers -----------------------------------------------------
__device__ __forceinline__ uint32_t smem_u32(const void* p) {
    return (uint32_t)__cvta_generic_to_shared(p);
}
__device__ __forceinline__ void ldsm4(uint32_t* r, uint32_t addr) {
    asm volatile("ldmatrix.sync.aligned.m8n8.x4.shared.b16 {%0,%1,%2,%3}, [%4];"
                 : "=r"(r[0]), "=r"(r[1]), "=r"(r[2]), "=r"(r[3]) : "r"(addr));
}
__device__ __forceinline__ void ldsm4t(uint32_t* r, uint32_t addr) {
    asm volatile("ldmatrix.sync.aligned.m8n8.x4.trans.shared.b16 {%0,%1,%2,%3}, [%4];"
                 : "=r"(r[0]), "=r"(r[1]), "=r"(r[2]), "=r"(r[3]) : "r"(addr));
}
__device__ __forceinline__ void mma_f16(float* d, const uint32_t* a, const uint32_t* b) {
    asm volatile(
        "mma.sync.aligned.m16n8k16.row.col.f32.f16.f16.f32 "
        "{%0,%1,%2,%3}, {%4,%5,%6,%7}, {%8,%9}, {%0,%1,%2,%3};"
        : "+f"(d[0]), "+f"(d[1]), "+f"(d[2]), "+f"(d[3])
        : "r"(a[0]), "r"(a[1]), "r"(a[2]), "r"(a[3]), "r"(b[0]), "r"(b[1]));
}
__device__ __forceinline__ void splitw(float x, f16& h, f16& l) {
    h = __float2half_rn(x);
    l = __float2half_rn(x - __half2float(h));
}
__device__ __forceinline__ void cpa16(uint32_t dst, const void* src) {
    asm volatile("cp.async.cg.shared.global [%0], [%1], 16;" :: "r"(dst), "l"(src));
}
__device__ __forceinline__ void cpa_commit() {
    asm volatile("cp.async.commit_group;" ::: "memory");
}
template<int N> __device__ __forceinline__ void cpa_wait() {
    asm volatile("cp.async.wait_group %0;" :: "n"(N) : "memory");
}

// Tile geometry
#define BM   128
#define BK   32
#define APAD 40     // 32 + 8 halves
#define BPAD 72     // 64 + 8 halves
#define A_ELE (BM * APAD)         // 5120
#define B_ELE (BK * BPAD)         // 2304

// ---------------- weight split (launches 0, 1) --------------------------------
__global__ void convert_w_kernel(const float* __restrict__ w,
                                 f16* __restrict__ wh, f16* __restrict__ wl,
                                 int n, int do_reset) {
    int i = blockIdx.x * blockDim.x + threadIdx.x;
    if (do_reset && blockIdx.x == 0 && threadIdx.x < NEXP) d_counts[threadIdx.x] = 0;
    int stride = gridDim.x * blockDim.x;
    for (; i < n; i += stride) {
        f16 h, l; splitw(w[i], h, l);
        wh[i] = h; wl[i] = l;
    }
}

// ---------------- patchify (launch 2) ----------------------------------------
__global__ void patchify_kernel(const float* __restrict__ x) {
    int idx = blockIdx.x * blockDim.x + threadIdx.x;
    if (idx >= NTOK * DDIM) return;
    int n = idx >> 9;
    int d = idx & 511;
    int b  = n >> 8;
    int h2 = (n >> 4) & 15;
    int w2 = n & 15;
    int c  = d >> 2;
    int ph = (d >> 1) & 1;
    int pw = d & 1;
    float v = x[(((b * CC + c) * HH) + h2 * 2 + ph) * WW + w2 * 2 + pw];
    d_xp[idx]  = v;
    d_xph[idx] = __float2half_rn(v);
}

// ---------------- router (launch 3) ------------------------------------------
__global__ void router_kernel(const float* __restrict__ rw) {
    __shared__ float rwT[NEXP * DDIM];
    int tid = threadIdx.x;
    for (int i = tid; i < NEXP * DDIM; i += blockDim.x) {
        int k = i >> 3, e = i & 7;
        rwT[e * DDIM + k] = rw[i];
    }
    __syncthreads();

    int warp = tid >> 5, lane = tid & 31;
    int n = blockIdx.x * 8 + warp;
    if (n >= NTOK) return;

    const float* xr = d_xp + (size_t)n * DDIM;
    float acc[NEXP];
#pragma unroll
    for (int e = 0; e < NEXP; e++) acc[e] = 0.f;
#pragma unroll
    for (int t = 0; t < DDIM / 32; t++) {
        int k = lane + t * 32;
        float xv = xr[k];
#pragma unroll
        for (int e = 0; e < NEXP; e++) acc[e] += xv * rwT[e * DDIM + k];
    }
#pragma unroll
    for (int e = 0; e < NEXP; e++) {
#pragma unroll
        for (int off = 16; off > 0; off >>= 1)
            acc[e] += __shfl_xor_sync(0xFFFFFFFFu, acc[e], off);
    }
    if (lane == 0) {
        int i0 = 0; float l0 = acc[0];
#pragma unroll
        for (int e = 1; e < NEXP; e++) if (acc[e] > l0) { l0 = acc[e]; i0 = e; }
        int i1 = -1; float l1 = -1e30f;
#pragma unroll
        for (int e = 0; e < NEXP; e++) if (e != i0 && acc[e] > l1) { l1 = acc[e]; i1 = e; }
        float g0 = 1.f / (1.f + expf(l1 - l0));
        float g1 = 1.f - g0;
        int r0 = atomicAdd(&d_counts[i0], 1);
        int r1 = atomicAdd(&d_counts[i1], 1);
        d_tok_e[n * 2 + 0] = i0; d_tok_r[n * 2 + 0] = r0; d_tok_g[n * 2 + 0] = g0;
        d_tok_e[n * 2 + 1] = i1; d_tok_r[n * 2 + 1] = r1; d_tok_g[n * 2 + 1] = g1;
    }
}

// ---------------- scatter + offsets (launch 4) --------------------------------
__global__ void scatter_kernel() {
    __shared__ int off_s[NEXP];
    int tid = threadIdx.x;
    if (tid == 0) {
        int s = 0;
        for (int e = 0; e < NEXP; e++) { off_s[e] = s; d_offsets[e] = s; s += d_counts[e]; }
    }
    __syncthreads();
    for (int n = tid; n < NTOK; n += blockDim.x) {
#pragma unroll
        for (int j = 0; j < 2; j++) {
            int e = d_tok_e[n * 2 + j];
            int pr = off_s[e] + d_tok_r[n * 2 + j];
            d_row_token[pr] = n;
            d_row_gate[pr]  = d_tok_g[n * 2 + j];
            d_tok_pr[n * 2 + j] = pr;
        }
    }
}

// ---------------- GEMM1 (launch 5): A fp16 x (w_hi + w_lo), fused SwiGLU -----
#define G1_STG (A_ELE + 4 * B_ELE)         // 14336 elems / stage
#define G1_SMEM (2 * G1_STG * 2)           // 57344 B
__global__ void __launch_bounds__(256) gemm1_kernel() {
    extern __shared__ f16 S[];
    __shared__ int rows_s[BM];

    int e    = blockIdx.z;
    int cnt  = d_counts[e];
    int row0 = blockIdx.y * BM;
    if (row0 >= cnt) return;
    int base = d_offsets[e];
    int jn0  = blockIdx.x * 64;

    int tid  = threadIdx.x;
    int lane = tid & 31;
    int wid  = tid >> 5;
    int wm   = wid >> 1;          // 0..3
    int wn   = wid & 1;           // 0..1
    int lm   = lane & 15;
    int lq   = lane >> 4;

    if (tid < BM) {
        int rr = row0 + tid;
        rows_s[tid] = d_row_token[base + ((rr < cnt) ? rr : (cnt - 1))];
    }
    __syncthreads();

    const f16* w1h = d_w1h + (size_t)e * DDIM * 2 * HID;
    const f16* w1l = d_w1l + (size_t)e * DDIM * 2 * HID;

    float accV[2][4][4], accG[2][4][4];
#pragma unroll
    for (int a = 0; a < 2; a++)
#pragma unroll
        for (int b = 0; b < 4; b++)
#pragma unroll
            for (int c = 0; c < 4; c++) { accV[a][b][c] = 0.f; accG[a][b][c] = 0.f; }

    int a_id0 = tid * 2;                       // 2 A-chunks per thread
    int b_r = tid >> 3, b_c = (tid & 7) * 8;   // 1 chunk per B array

#define G1_LOAD(st, k0)                                                          \
    {                                                                            \
        f16* Ah = S + (st) * G1_STG;                                             \
        f16* Bvh = Ah + A_ELE;                                                   \
        f16* Bvl = Bvh + B_ELE;                                                  \
        f16* Bgh = Bvl + B_ELE;                                                  \
        f16* Bgl = Bgh + B_ELE;                                                  \
        _Pragma("unroll")                                                        \
        for (int i = 0; i < 2; i++) {                                            \
            int id = a_id0 + i;                                                  \
            int r = id >> 2, c = (id & 3) * 8;                                   \
            size_t go = (size_t)rows_s[r] * DDIM + (k0) + c;                     \
            cpa16(smem_u32(Ah + r * APAD + c), d_xph + go);                      \
        }                                                                        \
        size_t gv = (size_t)((k0) + b_r) * (2 * HID) + jn0 + b_c;                \
        cpa16(smem_u32(Bvh + b_r * BPAD + b_c), w1h + gv);                       \
        cpa16(smem_u32(Bvl + b_r * BPAD + b_c), w1l + gv);                       \
        cpa16(smem_u32(Bgh + b_r * BPAD + b_c), w1h + gv + HID);                 \
        cpa16(smem_u32(Bgl + b_r * BPAD + b_c), w1l + gv + HID);                 \
    }

    G1_LOAD(0, 0);
    cpa_commit();

    for (int ch = 0; ch < DDIM / BK; ch++) {
        if (ch + 1 < DDIM / BK) {
            G1_LOAD((ch + 1) & 1, (ch + 1) * BK);
            cpa_commit();
            cpa_wait<1>();
        } else {
            cpa_wait<0>();
        }
        __syncthreads();

        f16* Ah = S + (ch & 1) * G1_STG;
        f16* Bvh = Ah + A_ELE;
        f16* Bvl = Bvh + B_ELE;
        f16* Bgh = Bvl + B_ELE;
        f16* Bgl = Bgh + B_ELE;

#pragma unroll
        for (int s = 0; s < 2; s++) {
            uint32_t ah[2][4];
#pragma unroll
            for (int tm = 0; tm < 2; tm++) {
                int ro = (wm * 32 + tm * 16 + lm) * APAD + s * 16 + lq * 8;
                ldsm4(ah[tm], smem_u32(Ah + ro));
            }
            uint32_t bvh[2][4], bvl[2][4], bgh[2][4], bgl[2][4];
#pragma unroll
            for (int nt = 0; nt < 2; nt++) {
                int bo = (s * 16 + lm) * BPAD + wn * 32 + nt * 16 + lq * 8;
                ldsm4t(bvh[nt], smem_u32(Bvh + bo));
                ldsm4t(bvl[nt], smem_u32(Bvl + bo));
                ldsm4t(bgh[nt], smem_u32(Bgh + bo));
                ldsm4t(bgl[nt], smem_u32(Bgl + bo));
            }
#pragma unroll
            for (int tm = 0; tm < 2; tm++) {
#pragma unroll
                for (int j = 0; j < 4; j++) {
                    int nt = j >> 1, o = (j & 1) * 2;
                    mma_f16(accV[tm][j], ah[tm], &bvh[nt][o]);
                    mma_f16(accV[tm][j], ah[tm], &bvl[nt][o]);
                    mma_f16(accG[tm][j], ah[tm], &bgh[nt][o]);
                    mma_f16(accG[tm][j], ah[tm], &bgl[nt][o]);
                }
            }
        }
        __syncthreads();
    }

    // epilogue: SwiGLU -> fp16 he
    int qr = lane >> 2, qc = lane & 3;
#pragma unroll
    for (int tm = 0; tm < 2; tm++) {
#pragma unroll
        for (int p = 0; p < 2; p++) {
            int rl = wm * 32 + tm * 16 + qr + p * 8;
            int r  = row0 + rl;
            if (r >= cnt) continue;
            size_t ho = (size_t)(base + r) * HID;
#pragma unroll
            for (int j = 0; j < 4; j++) {
                float v0 = accV[tm][j][p * 2], v1 = accV[tm][j][p * 2 + 1];
                float g0 = accG[tm][j][p * 2], g1 = accG[tm][j][p * 2 + 1];
                float o0 = v0 / (1.f + expf(-g0));
                float o1 = v1 / (1.f + expf(-g1));
                int col = jn0 + wn * 32 + j * 8 + qc * 2;
                *(f162*)&d_heh[ho + col] = __floats2half2_rn(o0, o1);
            }
        }
    }
}

// ---------------- GEMM2 (launch 6): he fp16 x (w2_hi + w2_lo), gated ---------
#define G2_STG (A_ELE + 2 * B_ELE)         // 9728 elems / stage
#define G2_SMEM (2 * G2_STG * 2)           // 38912 B
__global__ void __launch_bounds__(256) gemm2_kernel() {
    extern __shared__ f16 S[];
    __shared__ float gate_s[BM];

    int e    = blockIdx.z;
    int cnt  = d_counts[e];
    int row0 = blockIdx.y * BM;
    if (row0 >= cnt) return;
    int base = d_offsets[e];
    int n0   = blockIdx.x * 64;

    int tid  = threadIdx.x;
    int lane = tid & 31;
    int wid  = tid >> 5;
    int wm   = wid >> 1;
    int wn   = wid & 1;
    int lm   = lane & 15;
    int lq   = lane >> 4;

    if (tid < BM) {
        int rr = row0 + tid;
        gate_s[tid] = (rr < cnt) ? d_row_gate[base + rr] : 0.f;
    }
    __syncthreads();

    const f16* w2h = d_w2h + (size_t)e * HID * DDIM;
    const f16* w2l = d_w2l + (size_t)e * HID * DDIM;

    float acc[2][4][4];
#pragma unroll
    for (int a = 0; a < 2; a++)
#pragma unroll
        for (int b = 0; b < 4; b++)
#pragma unroll
            for (int c = 0; c < 4; c++) acc[a][b][c] = 0.f;

    int a_id0 = tid * 2;
    int b_r = tid >> 3, b_c = (tid & 7) * 8;

#define G2_LOAD(st, k0)                                                          \
    {                                                                            \
        f16* Ah = S + (st) * G2_STG;                                             \
        f16* Bh = Ah + A_ELE;                                                    \
        f16* Bl = Bh + B_ELE;                                                    \
        _Pragma("unroll")                                                        \
        for (int i = 0; i < 2; i++) {                                            \
            int id = a_id0 + i;                                                  \
            int r = id >> 2, c = (id & 3) * 8;                                   \
            int rr = row0 + r; if (rr >= cnt) rr = cnt - 1;                      \
            size_t go = (size_t)(base + rr) * HID + (k0) + c;                    \
            cpa16(smem_u32(Ah + r * APAD + c), d_heh + go);                      \
        }                                                                        \
        size_t gb = (size_t)((k0) + b_r) * DDIM + n0 + b_c;                      \
        cpa16(smem_u32(Bh + b_r * BPAD + b_c), w2h + gb);                        \
        cpa16(smem_u32(Bl + b_r * BPAD + b_c), w2l + gb);                        \
    }

    G2_LOAD(0, 0);
    cpa_commit();

    for (int ch = 0; ch < HID / BK; ch++) {
        if (ch + 1 < HID / BK) {
            G2_LOAD((ch + 1) & 1, (ch + 1) * BK);
            cpa_commit();
            cpa_wait<1>();
        } else {
            cpa_wait<0>();
        }
        __syncthreads();

        f16* Ah = S + (ch & 1) * G2_STG;
        f16* Bh = Ah + A_ELE;
        f16* Bl = Bh + B_ELE;

#pragma unroll
        for (int s = 0; s < 2; s++) {
            uint32_t ah[2][4];
#pragma unroll
            for (int tm = 0; tm < 2; tm++) {
                int ro = (wm * 32 + tm * 16 + lm) * APAD + s * 16 + lq * 8;
                ldsm4(ah[tm], smem_u32(Ah + ro));
            }
            uint32_t bh[2][4], bl[2][4];
#pragma unroll
            for (int nt = 0; nt < 2; nt++) {
                int bo = (s * 16 + lm) * BPAD + wn * 32 + nt * 16 + lq * 8;
                ldsm4t(bh[nt], smem_u32(Bh + bo));
                ldsm4t(bl[nt], smem_u32(Bl + bo));
            }
#pragma unroll
            for (int tm = 0; tm < 2; tm++) {
#pragma unroll
                for (int j = 0; j < 4; j++) {
                    int nt = j >> 1, o = (j & 1) * 2;
                    mma_f16(acc[tm][j], ah[tm], &bh[nt][o]);
                    mma_f16(acc[tm][j], ah[tm], &bl[nt][o]);
                }
            }
        }
        __syncthreads();
    }

    int qr = lane >> 2, qc = lane & 3;
#pragma unroll
    for (int tm = 0; tm < 2; tm++) {
#pragma unroll
        for (int p = 0; p < 2; p++) {
            int rl = wm * 32 + tm * 16 + qr + p * 8;
            int r  = row0 + rl;
            if (r >= cnt) continue;
            float g = gate_s[rl];
            size_t po = (size_t)(base + r) * DDIM;
#pragma unroll
            for (int j = 0; j < 4; j++) {
                int col = n0 + wn * 32 + j * 8 + qc * 2;
                float2 o = make_float2(g * acc[tm][j][p * 2], g * acc[tm][j][p * 2 + 1]);
                *(float2*)&d_po[po + col] = o;
            }
        }
    }
}

// ---------------- combine (launch 7) -----------------------------------------
__global__ void combine_kernel(float* __restrict__ y) {
    int idx = blockIdx.x * blockDim.x + threadIdx.x;
    if (idx >= NTOK * DDIM) return;
    int w = idx & 31;
    int h = (idx >> 5) & 31;
    int c = (idx >> 10) & 127;
    int b = idx >> 17;
    int n = (b << 8) + ((h >> 1) << 4) + (w >> 1);
    int d = (c << 2) + ((h & 1) << 1) + (w & 1);
    int pr0 = d_tok_pr[n * 2 + 0];
    int pr1 = d_tok_pr[n * 2 + 1];
    y[idx] = d_po[(size_t)pr0 * DDIM + d] + d_po[(size_t)pr1 * DDIM + d];
}

// ---------------- launch -----------------------------------------------------
extern "C" void kernel_launch(void* const* d_in, const int* in_sizes, int n_in,
                              void* d_out, int out_size) {
    const float* x  = (const float*)d_in[0];
    const float* rw = (const float*)d_in[1];
    const float* w1 = (const float*)d_in[2];
    const float* w2 = (const float*)d_in[3];
    float* y = (float*)d_out;

    cudaFuncSetAttribute(gemm1_kernel, cudaFuncAttributeMaxDynamicSharedMemorySize, G1_SMEM);
    cudaFuncSetAttribute(gemm2_kernel, cudaFuncAttributeMaxDynamicSharedMemorySize, G2_SMEM);

    f16 *w1h, *w1l, *w2h, *w2l;
    cudaGetSymbolAddress((void**)&w1h, d_w1h);
    cudaGetSymbolAddress((void**)&w1l, d_w1l);
    cudaGetSymbolAddress((void**)&w2h, d_w2h);
    cudaGetSymbolAddress((void**)&w2l, d_w2l);

    convert_w_kernel<<<1024, 256>>>(w1, w1h, w1l, NEXP * DDIM * 2 * HID, 1);  // 0 (+reset)
    convert_w_kernel<<<1024, 256>>>(w2, w2h, w2l, NEXP * HID * DDIM, 0);      // 1
    patchify_kernel<<<(NTOK * DDIM + 255) / 256, 256>>>(x);                   // 2
    router_kernel<<<NTOK / 8, 256>>>(rw);                                     // 3
    scatter_kernel<<<1, 256>>>();                                             // 4
    gemm1_kernel<<<dim3(HID / 64, NTOK / BM, NEXP), 256, G1_SMEM>>>();        // 5
    gemm2_kernel<<<dim3(DDIM / 64, NTOK / BM, NEXP), 256, G2_SMEM>>>();       // 6
    combine_kernel<<<(NTOK * DDIM + 255) / 256, 256>>>(y);                    // 7
}

// round 8
// speedup vs baseline: 4.9512x; 1.2638x over previous
#include <cuda_runtime.h>
#include <cuda_fp16.h>
#include <math.h>
#include <stdint.h>

// Problem constants
#define NTOK 4096
#define DDIM 512
#define NEXP 8
#define HID  1024
#define NPAIR (NTOK * 2)
#define CC   128
#define HH   32
#define WW   32

typedef __half  f16;
typedef __half2 f162;

// ---------------- static device scratch --------------------------------------
__device__ float d_xp [NTOK * DDIM];                     // fp32 tokens (router)
__device__ __align__(256) f16 d_xph[NTOK * DDIM];        // fp16 tokens (GEMM1 A)
__device__ __align__(256) f16 d_heh[NPAIR * HID];        // fp16 swiglu acts (GEMM2 A)
__device__ float d_po [NPAIR * DDIM];                    // gate-scaled outputs
__device__ __align__(256) f16 d_w1h[NEXP * DDIM * 2 * HID];  // w1 fp16
__device__ __align__(256) f16 d_w2h[NEXP * HID * DDIM];      // w2 fp16
__device__ int   d_counts[NEXP];
__device__ int   d_offsets[NEXP];
__device__ int   d_tok_e[NTOK * 2];
__device__ int   d_tok_r[NTOK * 2];
__device__ float d_tok_g[NTOK * 2];
__device__ int   d_tok_pr[NTOK * 2];
__device__ int   d_row_token[NPAIR];
__device__ float d_row_gate[NPAIR];

// ---------------- helpers -----------------------------------------------------
__device__ __forceinline__ uint32_t smem_u32(const void* p) {
    return (uint32_t)__cvta_generic_to_shared(p);
}
__device__ __forceinline__ void ldsm4(uint32_t* r, uint32_t addr) {
    asm volatile("ldmatrix.sync.aligned.m8n8.x4.shared.b16 {%0,%1,%2,%3}, [%4];"
                 : "=r"(r[0]), "=r"(r[1]), "=r"(r[2]), "=r"(r[3]) : "r"(addr));
}
__device__ __forceinline__ void ldsm4t(uint32_t* r, uint32_t addr) {
    asm volatile("ldmatrix.sync.aligned.m8n8.x4.trans.shared.b16 {%0,%1,%2,%3}, [%4];"
                 : "=r"(r[0]), "=r"(r[1]), "=r"(r[2]), "=r"(r[3]) : "r"(addr));
}
__device__ __forceinline__ void mma_f16(float* d, const uint32_t* a, const uint32_t* b) {
    asm volatile(
        "mma.sync.aligned.m16n8k16.row.col.f32.f16.f16.f32 "
        "{%0,%1,%2,%3}, {%4,%5,%6,%7}, {%8,%9}, {%0,%1,%2,%3};"
        : "+f"(d[0]), "+f"(d[1]), "+f"(d[2]), "+f"(d[3])
        : "r"(a[0]), "r"(a[1]), "r"(a[2]), "r"(a[3]), "r"(b[0]), "r"(b[1]));
}
__device__ __forceinline__ void cpa16(uint32_t dst, const void* src) {
    asm volatile("cp.async.cg.shared.global [%0], [%1], 16;" :: "r"(dst), "l"(src));
}
__device__ __forceinline__ void cpa_commit() {
    asm volatile("cp.async.commit_group;" ::: "memory");
}
template<int N> __device__ __forceinline__ void cpa_wait() {
    asm volatile("cp.async.wait_group %0;" :: "n"(N) : "memory");
}

// Tile geometry
#define BM   128
#define BK   32
#define APAD 40     // 32 + 8 halves
#define BPAD 72     // 64 + 8 halves
#define A_ELE (BM * APAD)         // 5120
#define B_ELE (BK * BPAD)         // 2304

// ---------------- weight cast (launches 0, 1) ---------------------------------
__global__ void convert_w_kernel(const float* __restrict__ w,
                                 f16* __restrict__ wh, int n, int do_reset) {
    int i = blockIdx.x * blockDim.x + threadIdx.x;
    if (do_reset && blockIdx.x == 0 && threadIdx.x < NEXP) d_counts[threadIdx.x] = 0;
    int stride = gridDim.x * blockDim.x;
    for (; i < n; i += stride) wh[i] = __float2half_rn(w[i]);
}

// ---------------- patchify (launch 2) ----------------------------------------
__global__ void patchify_kernel(const float* __restrict__ x) {
    int idx = blockIdx.x * blockDim.x + threadIdx.x;
    if (idx >= NTOK * DDIM) return;
    int n = idx >> 9;
    int d = idx & 511;
    int b  = n >> 8;
    int h2 = (n >> 4) & 15;
    int w2 = n & 15;
    int c  = d >> 2;
    int ph = (d >> 1) & 1;
    int pw = d & 1;
    float v = x[(((b * CC + c) * HH) + h2 * 2 + ph) * WW + w2 * 2 + pw];
    d_xp[idx]  = v;
    d_xph[idx] = __float2half_rn(v);
}

// ---------------- router (launch 3) ------------------------------------------
__global__ void router_kernel(const float* __restrict__ rw) {
    __shared__ float rwT[NEXP * DDIM];
    int tid = threadIdx.x;
    for (int i = tid; i < NEXP * DDIM; i += blockDim.x) {
        int k = i >> 3, e = i & 7;
        rwT[e * DDIM + k] = rw[i];
    }
    __syncthreads();

    int warp = tid >> 5, lane = tid & 31;
    int n = blockIdx.x * 8 + warp;
    if (n >= NTOK) return;

    const float* xr = d_xp + (size_t)n * DDIM;
    float acc[NEXP];
#pragma unroll
    for (int e = 0; e < NEXP; e++) acc[e] = 0.f;
#pragma unroll
    for (int t = 0; t < DDIM / 32; t++) {
        int k = lane + t * 32;
        float xv = xr[k];
#pragma unroll
        for (int e = 0; e < NEXP; e++) acc[e] += xv * rwT[e * DDIM + k];
    }
#pragma unroll
    for (int e = 0; e < NEXP; e++) {
#pragma unroll
        for (int off = 16; off > 0; off >>= 1)
            acc[e] += __shfl_xor_sync(0xFFFFFFFFu, acc[e], off);
    }
    if (lane == 0) {
        int i0 = 0; float l0 = acc[0];
#pragma unroll
        for (int e = 1; e < NEXP; e++) if (acc[e] > l0) { l0 = acc[e]; i0 = e; }
        int i1 = -1; float l1 = -1e30f;
#pragma unroll
        for (int e = 0; e < NEXP; e++) if (e != i0 && acc[e] > l1) { l1 = acc[e]; i1 = e; }
        float g0 = 1.f / (1.f + expf(l1 - l0));
        float g1 = 1.f - g0;
        int r0 = atomicAdd(&d_counts[i0], 1);
        int r1 = atomicAdd(&d_counts[i1], 1);
        d_tok_e[n * 2 + 0] = i0; d_tok_r[n * 2 + 0] = r0; d_tok_g[n * 2 + 0] = g0;
        d_tok_e[n * 2 + 1] = i1; d_tok_r[n * 2 + 1] = r1; d_tok_g[n * 2 + 1] = g1;
    }
}

// ---------------- scatter + offsets (launch 4) --------------------------------
__global__ void scatter_kernel() {
    __shared__ int off_s[NEXP];
    int tid = threadIdx.x;
    if (tid == 0) {
        int s = 0;
        for (int e = 0; e < NEXP; e++) { off_s[e] = s; d_offsets[e] = s; s += d_counts[e]; }
    }
    __syncthreads();
    for (int n = tid; n < NTOK; n += blockDim.x) {
#pragma unroll
        for (int j = 0; j < 2; j++) {
            int e = d_tok_e[n * 2 + j];
            int pr = off_s[e] + d_tok_r[n * 2 + j];
            d_row_token[pr] = n;
            d_row_gate[pr]  = d_tok_g[n * 2 + j];
            d_tok_pr[n * 2 + j] = pr;
        }
    }
}

// ---------------- GEMM1 (launch 5): A fp16 x w1 fp16, fused SwiGLU -----------
#define G1_STG (A_ELE + 2 * B_ELE)         // 9728 elems / stage
#define G1_SMEM (2 * G1_STG * 2)           // 38912 B
__global__ void __launch_bounds__(256) gemm1_kernel() {
    extern __shared__ f16 S[];
    __shared__ int rows_s[BM];

    int e    = blockIdx.z;
    int cnt  = d_counts[e];
    int row0 = blockIdx.y * BM;
    if (row0 >= cnt) return;
    int base = d_offsets[e];
    int jn0  = blockIdx.x * 64;

    int tid  = threadIdx.x;
    int lane = tid & 31;
    int wid  = tid >> 5;
    int wm   = wid >> 1;          // 0..3
    int wn   = wid & 1;           // 0..1
    int lm   = lane & 15;
    int lq   = lane >> 4;

    if (tid < BM) {
        int rr = row0 + tid;
        rows_s[tid] = d_row_token[base + ((rr < cnt) ? rr : (cnt - 1))];
    }
    __syncthreads();

    const f16* w1h = d_w1h + (size_t)e * DDIM * 2 * HID;

    float accV[2][4][4], accG[2][4][4];
#pragma unroll
    for (int a = 0; a < 2; a++)
#pragma unroll
        for (int b = 0; b < 4; b++)
#pragma unroll
            for (int c = 0; c < 4; c++) { accV[a][b][c] = 0.f; accG[a][b][c] = 0.f; }

    int a_id0 = tid * 2;                       // 2 A-chunks per thread
    int b_r = tid >> 3, b_c = (tid & 7) * 8;   // 1 chunk per B array

#define G1_LOAD(st, k0)                                                          \
    {                                                                            \
        f16* Ah = S + (st) * G1_STG;                                             \
        f16* Bvh = Ah + A_ELE;                                                   \
        f16* Bgh = Bvh + B_ELE;                                                  \
        _Pragma("unroll")                                                        \
        for (int i = 0; i < 2; i++) {                                            \
            int id = a_id0 + i;                                                  \
            int r = id >> 2, c = (id & 3) * 8;                                   \
            size_t go = (size_t)rows_s[r] * DDIM + (k0) + c;                     \
            cpa16(smem_u32(Ah + r * APAD + c), d_xph + go);                      \
        }                                                                        \
        size_t gv = (size_t)((k0) + b_r) * (2 * HID) + jn0 + b_c;                \
        cpa16(smem_u32(Bvh + b_r * BPAD + b_c), w1h + gv);                       \
        cpa16(smem_u32(Bgh + b_r * BPAD + b_c), w1h + gv + HID);                 \
    }

    G1_LOAD(0, 0);
    cpa_commit();

    for (int ch = 0; ch < DDIM / BK; ch++) {
        if (ch + 1 < DDIM / BK) {
            G1_LOAD((ch + 1) & 1, (ch + 1) * BK);
            cpa_commit();
            cpa_wait<1>();
        } else {
            cpa_wait<0>();
        }
        __syncthreads();

        f16* Ah = S + (ch & 1) * G1_STG;
        f16* Bvh = Ah + A_ELE;
        f16* Bgh = Bvh + B_ELE;

#pragma unroll
        for (int s = 0; s < 2; s++) {
            uint32_t ah[2][4];
#pragma unroll
            for (int tm = 0; tm < 2; tm++) {
                int ro = (wm * 32 + tm * 16 + lm) * APAD + s * 16 + lq * 8;
                ldsm4(ah[tm], smem_u32(Ah + ro));
            }
            uint32_t bvh[2][4], bgh[2][4];
#pragma unroll
            for (int nt = 0; nt < 2; nt++) {
                int bo = (s * 16 + lm) * BPAD + wn * 32 + nt * 16 + lq * 8;
                ldsm4t(bvh[nt], smem_u32(Bvh + bo));
                ldsm4t(bgh[nt], smem_u32(Bgh + bo));
            }
#pragma unroll
            for (int tm = 0; tm < 2; tm++) {
#pragma unroll
                for (int j = 0; j < 4; j++) {
                    int nt = j >> 1, o = (j & 1) * 2;
                    mma_f16(accV[tm][j], ah[tm], &bvh[nt][o]);
                    mma_f16(accG[tm][j], ah[tm], &bgh[nt][o]);
                }
            }
        }
        __syncthreads();
    }

    // epilogue: SwiGLU -> fp16 he
    int qr = lane >> 2, qc = lane & 3;
#pragma unroll
    for (int tm = 0; tm < 2; tm++) {
#pragma unroll
        for (int p = 0; p < 2; p++) {
            int rl = wm * 32 + tm * 16 + qr + p * 8;
            int r  = row0 + rl;
            if (r >= cnt) continue;
            size_t ho = (size_t)(base + r) * HID;
#pragma unroll
            for (int j = 0; j < 4; j++) {
                float v0 = accV[tm][j][p * 2], v1 = accV[tm][j][p * 2 + 1];
                float g0 = accG[tm][j][p * 2], g1 = accG[tm][j][p * 2 + 1];
                float o0 = v0 / (1.f + expf(-g0));
                float o1 = v1 / (1.f + expf(-g1));
                int col = jn0 + wn * 32 + j * 8 + qc * 2;
                *(f162*)&d_heh[ho + col] = __floats2half2_rn(o0, o1);
            }
        }
    }
}

// ---------------- GEMM2 (launch 6): he fp16 x w2 fp16, gated -----------------
#define G2_STG (A_ELE + B_ELE)             // 7424 elems / stage
#define G2_SMEM (2 * G2_STG * 2)           // 29696 B
__global__ void __launch_bounds__(256) gemm2_kernel() {
    extern __shared__ f16 S[];
    __shared__ float gate_s[BM];

    int e    = blockIdx.z;
    int cnt  = d_counts[e];
    int row0 = blockIdx.y * BM;
    if (row0 >= cnt) return;
    int base = d_offsets[e];
    int n0   = blockIdx.x * 64;

    int tid  = threadIdx.x;
    int lane = tid & 31;
    int wid  = tid >> 5;
    int wm   = wid >> 1;
    int wn   = wid & 1;
    int lm   = lane & 15;
    int lq   = lane >> 4;

    if (tid < BM) {
        int rr = row0 + tid;
        gate_s[tid] = (rr < cnt) ? d_row_gate[base + rr] : 0.f;
    }
    __syncthreads();

    const f16* w2h = d_w2h + (size_t)e * HID * DDIM;

    float acc[2][4][4];
#pragma unroll
    for (int a = 0; a < 2; a++)
#pragma unroll
        for (int b = 0; b < 4; b++)
#pragma unroll
            for (int c = 0; c < 4; c++) acc[a][b][c] = 0.f;

    int a_id0 = tid * 2;
    int b_r = tid >> 3, b_c = (tid & 7) * 8;

#define G2_LOAD(st, k0)                                                          \
    {                                                                            \
        f16* Ah = S + (st) * G2_STG;                                             \
        f16* Bh = Ah + A_ELE;                                                    \
        _Pragma("unroll")                                                        \
        for (int i = 0; i < 2; i++) {                                            \
            int id = a_id0 + i;                                                  \
            int r = id >> 2, c = (id & 3) * 8;                                   \
            int rr = row0 + r; if (rr >= cnt) rr = cnt - 1;                      \
            size_t go = (size_t)(base + rr) * HID + (k0) + c;                    \
            cpa16(smem_u32(Ah + r * APAD + c), d_heh + go);                      \
        }                                                                        \
        size_t gb = (size_t)((k0) + b_r) * DDIM + n0 + b_c;                      \
        cpa16(smem_u32(Bh + b_r * BPAD + b_c), w2h + gb);                        \
    }

    G2_LOAD(0, 0);
    cpa_commit();

    for (int ch = 0; ch < HID / BK; ch++) {
        if (ch + 1 < HID / BK) {
            G2_LOAD((ch + 1) & 1, (ch + 1) * BK);
            cpa_commit();
            cpa_wait<1>();
        } else {
            cpa_wait<0>();
        }
        __syncthreads();

        f16* Ah = S + (ch & 1) * G2_STG;
        f16* Bh = Ah + A_ELE;

#pragma unroll
        for (int s = 0; s < 2; s++) {
            uint32_t ah[2][4];
#pragma unroll
            for (int tm = 0; tm < 2; tm++) {
                int ro = (wm * 32 + tm * 16 + lm) * APAD + s * 16 + lq * 8;
                ldsm4(ah[tm], smem_u32(Ah + ro));
            }
            uint32_t bh[2][4];
#pragma unroll
            for (int nt = 0; nt < 2; nt++) {
                int bo = (s * 16 + lm) * BPAD + wn * 32 + nt * 16 + lq * 8;
                ldsm4t(bh[nt], smem_u32(Bh + bo));
            }
#pragma unroll
            for (int tm = 0; tm < 2; tm++) {
#pragma unroll
                for (int j = 0; j < 4; j++) {
                    int nt = j >> 1, o = (j & 1) * 2;
                    mma_f16(acc[tm][j], ah[tm], &bh[nt][o]);
                }
            }
        }
        __syncthreads();
    }

    int qr = lane >> 2, qc = lane & 3;
#pragma unroll
    for (int tm = 0; tm < 2; tm++) {
#pragma unroll
        for (int p = 0; p < 2; p++) {
            int rl = wm * 32 + tm * 16 + qr + p * 8;
            int r  = row0 + rl;
            if (r >= cnt) continue;
            float g = gate_s[rl];
            size_t po = (size_t)(base + r) * DDIM;
#pragma unroll
            for (int j = 0; j < 4; j++) {
                int col = n0 + wn * 32 + j * 8 + qc * 2;
                float2 o = make_float2(g * acc[tm][j][p * 2], g * acc[tm][j][p * 2 + 1]);
                *(float2*)&d_po[po + col] = o;
            }
        }
    }
}

// ---------------- combine (launch 7) -----------------------------------------
__global__ void combine_kernel(float* __restrict__ y) {
    int idx = blockIdx.x * blockDim.x + threadIdx.x;
    if (idx >= NTOK * DDIM) return;
    int w = idx & 31;
    int h = (idx >> 5) & 31;
    int c = (idx >> 10) & 127;
    int b = idx >> 17;
    int n = (b << 8) + ((h >> 1) << 4) + (w >> 1);
    int d = (c << 2) + ((h & 1) << 1) + (w & 1);
    int pr0 = d_tok_pr[n * 2 + 0];
    int pr1 = d_tok_pr[n * 2 + 1];
    y[idx] = d_po[(size_t)pr0 * DDIM + d] + d_po[(size_t)pr1 * DDIM + d];
}

// ---------------- launch -----------------------------------------------------
extern "C" void kernel_launch(void* const* d_in, const int* in_sizes, int n_in,
                              void* d_out, int out_size) {
    const float* x  = (const float*)d_in[0];
    const float* rw = (const float*)d_in[1];
    const float* w1 = (const float*)d_in[2];
    const float* w2 = (const float*)d_in[3];
    float* y = (float*)d_out;

    cudaFuncSetAttribute(gemm1_kernel, cudaFuncAttributeMaxDynamicSharedMemorySize, G1_SMEM);
    cudaFuncSetAttribute(gemm2_kernel, cudaFuncAttributeMaxDynamicSharedMemorySize, G2_SMEM);

    f16 *w1h, *w2h;
    cudaGetSymbolAddress((void**)&w1h, d_w1h);
    cudaGetSymbolAddress((void**)&w2h, d_w2h);

    convert_w_kernel<<<1024, 256>>>(w1, w1h, NEXP * DDIM * 2 * HID, 1);       // 0 (+reset)
    convert_w_kernel<<<1024, 256>>>(w2, w2h, NEXP * HID * DDIM, 0);           // 1
    patchify_kernel<<<(NTOK * DDIM + 255) / 256, 256>>>(x);                   // 2
    router_kernel<<<NTOK / 8, 256>>>(rw);                                     // 3
    scatter_kernel<<<1, 256>>>();                                             // 4
    gemm1_kernel<<<dim3(HID / 64, NTOK / BM, NEXP), 256, G1_SMEM>>>();        // 5
    gemm2_kernel<<<dim3(DDIM / 64, NTOK / BM, NEXP), 256, G2_SMEM>>>();       // 6
    combine_kernel<<<(NTOK * DDIM + 255) / 256, 256>>>(y);                    // 7
}

// round 11
// speedup vs baseline: 5.6352x; 1.1381x over previous
#include <cuda_runtime.h>
#include <cuda_fp16.h>
#include <math.h>
#include <stdint.h>

// Problem constants
#define NTOK 4096
#define DDIM 512
#define NEXP 8
#define HID  1024
#define NPAIR (NTOK * 2)
#define CC   128
#define HH   32
#define WW   32

typedef __half  f16;
typedef __half2 f162;

// ---------------- static device scratch --------------------------------------
__device__ float d_xp [NTOK * DDIM];                     // fp32 tokens (router)
__device__ __align__(256) f16 d_xph[NTOK * DDIM];        // fp16 tokens (GEMM1 A)
__device__ __align__(256) f16 d_heh[NPAIR * HID];        // fp16 swiglu acts (GEMM2 A)
__device__ float d_po [NPAIR * DDIM];                    // gate-scaled outputs
__device__ __align__(256) f16 d_w1h[NEXP * DDIM * 2 * HID];  // w1 fp16
__device__ __align__(256) f16 d_w2h[NEXP * HID * DDIM];      // w2 fp16
__device__ int   d_counts[NEXP];
__device__ int   d_offsets[NEXP];
__device__ int   d_tok_e[NTOK * 2];
__device__ int   d_tok_r[NTOK * 2];
__device__ float d_tok_g[NTOK * 2];
__device__ int   d_tok_pr[NTOK * 2];
__device__ int   d_row_token[NPAIR];
__device__ float d_row_gate[NPAIR];

// ---------------- helpers -----------------------------------------------------
__device__ __forceinline__ uint32_t smem_u32(const void* p) {
    return (uint32_t)__cvta_generic_to_shared(p);
}
__device__ __forceinline__ void ldsm4(uint32_t* r, uint32_t addr) {
    asm volatile("ldmatrix.sync.aligned.m8n8.x4.shared.b16 {%0,%1,%2,%3}, [%4];"
                 : "=r"(r[0]), "=r"(r[1]), "=r"(r[2]), "=r"(r[3]) : "r"(addr));
}
__device__ __forceinline__ void ldsm4t(uint32_t* r, uint32_t addr) {
    asm volatile("ldmatrix.sync.aligned.m8n8.x4.trans.shared.b16 {%0,%1,%2,%3}, [%4];"
                 : "=r"(r[0]), "=r"(r[1]), "=r"(r[2]), "=r"(r[3]) : "r"(addr));
}
__device__ __forceinline__ void mma_f16(float* d, const uint32_t* a, const uint32_t* b) {
    asm volatile(
        "mma.sync.aligned.m16n8k16.row.col.f32.f16.f16.f32 "
        "{%0,%1,%2,%3}, {%4,%5,%6,%7}, {%8,%9}, {%0,%1,%2,%3};"
        : "+f"(d[0]), "+f"(d[1]), "+f"(d[2]), "+f"(d[3])
        : "r"(a[0]), "r"(a[1]), "r"(a[2]), "r"(a[3]), "r"(b[0]), "r"(b[1]));
}
__device__ __forceinline__ void cpa16(uint32_t dst, const void* src) {
    asm volatile("cp.async.cg.shared.global [%0], [%1], 16;" :: "r"(dst), "l"(src));
}
__device__ __forceinline__ void cpa_commit() {
    asm volatile("cp.async.commit_group;" ::: "memory");
}
template<int N> __device__ __forceinline__ void cpa_wait() {
    asm volatile("cp.async.wait_group %0;" :: "n"(N) : "memory");
}

// Tile geometry
#define BM    128
#define BK    64
#define APAD  72     // 64 + 8 halves (144B row stride: conflict-free ldsm)
#define B1PAD 72     // G1 B: 64-wide + 8
#define B2PAD 136    // G2 B: 128-wide + 8
#define A_ELE  (BM * APAD)        // 9216
#define B1_ELE (BK * B1PAD)       // 4608
#define B2_ELE (BK * B2PAD)       // 8704

// ---------------- weight cast + reset (launch 0) ------------------------------
__global__ void convert_w_kernel(const float* __restrict__ w1,
                                 const float* __restrict__ w2,
                                 f16* __restrict__ w1h, f16* __restrict__ w2h) {
    const int n1 = NEXP * DDIM * 2 * HID;
    const int n2 = NEXP * HID * DDIM;
    if (blockIdx.x == 0 && threadIdx.x < NEXP) d_counts[threadIdx.x] = 0;
    int i = blockIdx.x * blockDim.x + threadIdx.x;
    int stride = gridDim.x * blockDim.x;
    for (; i < n1 + n2; i += stride) {
        if (i < n1) w1h[i] = __float2half_rn(w1[i]);
        else        w2h[i - n1] = __float2half_rn(w2[i - n1]);
    }
}

// ---------------- patchify (launch 1) ----------------------------------------
__global__ void patchify_kernel(const float* __restrict__ x) {
    int idx = blockIdx.x * blockDim.x + threadIdx.x;
    if (idx >= NTOK * DDIM) return;
    int n = idx >> 9;
    int d = idx & 511;
    int b  = n >> 8;
    int h2 = (n >> 4) & 15;
    int w2 = n & 15;
    int c  = d >> 2;
    int ph = (d >> 1) & 1;
    int pw = d & 1;
    float v = x[(((b * CC + c) * HH) + h2 * 2 + ph) * WW + w2 * 2 + pw];
    d_xp[idx]  = v;
    d_xph[idx] = __float2half_rn(v);
}

// ---------------- router (launch 2) ------------------------------------------
__global__ void router_kernel(const float* __restrict__ rw) {
    __shared__ float rwT[NEXP * DDIM];
    int tid = threadIdx.x;
    for (int i = tid; i < NEXP * DDIM; i += blockDim.x) {
        int k = i >> 3, e = i & 7;
        rwT[e * DDIM + k] = rw[i];
    }
    __syncthreads();

    int warp = tid >> 5, lane = tid & 31;
    int n = blockIdx.x * 8 + warp;
    if (n >= NTOK) return;

    const float* xr = d_xp + (size_t)n * DDIM;
    float acc[NEXP];
#pragma unroll
    for (int e = 0; e < NEXP; e++) acc[e] = 0.f;
#pragma unroll
    for (int t = 0; t < DDIM / 32; t++) {
        int k = lane + t * 32;
        float xv = xr[k];
#pragma unroll
        for (int e = 0; e < NEXP; e++) acc[e] += xv * rwT[e * DDIM + k];
    }
#pragma unroll
    for (int e = 0; e < NEXP; e++) {
#pragma unroll
        for (int off = 16; off > 0; off >>= 1)
            acc[e] += __shfl_xor_sync(0xFFFFFFFFu, acc[e], off);
    }
    if (lane == 0) {
        int i0 = 0; float l0 = acc[0];
#pragma unroll
        for (int e = 1; e < NEXP; e++) if (acc[e] > l0) { l0 = acc[e]; i0 = e; }
        int i1 = -1; float l1 = -1e30f;
#pragma unroll
        for (int e = 0; e < NEXP; e++) if (e != i0 && acc[e] > l1) { l1 = acc[e]; i1 = e; }
        float g0 = 1.f / (1.f + expf(l1 - l0));
        float g1 = 1.f - g0;
        int r0 = atomicAdd(&d_counts[i0], 1);
        int r1 = atomicAdd(&d_counts[i1], 1);
        d_tok_e[n * 2 + 0] = i0; d_tok_r[n * 2 + 0] = r0; d_tok_g[n * 2 + 0] = g0;
        d_tok_e[n * 2 + 1] = i1; d_tok_r[n * 2 + 1] = r1; d_tok_g[n * 2 + 1] = g1;
    }
}

// ---------------- scatter + offsets (launch 3) --------------------------------
__global__ void scatter_kernel() {
    __shared__ int off_s[NEXP];
    int tid = threadIdx.x;
    if (tid == 0) {
        int s = 0;
        for (int e = 0; e < NEXP; e++) { off_s[e] = s; d_offsets[e] = s; s += d_counts[e]; }
    }
    __syncthreads();
    for (int n = tid; n < NTOK; n += blockDim.x) {
#pragma unroll
        for (int j = 0; j < 2; j++) {
            int e = d_tok_e[n * 2 + j];
            int pr = off_s[e] + d_tok_r[n * 2 + j];
            d_row_token[pr] = n;
            d_row_gate[pr]  = d_tok_g[n * 2 + j];
            d_tok_pr[n * 2 + j] = pr;
        }
    }
}

// ---------------- GEMM1 (launch 4): 128x(64v+64g), BK=64, fused SwiGLU -------
#define G1_STG (A_ELE + 2 * B1_ELE)        // 18432 elems / stage
#define G1_SMEM (2 * G1_STG * 2)           // 73728 B
__global__ void __launch_bounds__(256) gemm1_kernel() {
    extern __shared__ f16 S[];
    __shared__ int rows_s[BM];

    int e    = blockIdx.z;
    int cnt  = d_counts[e];
    int row0 = blockIdx.y * BM;
    if (row0 >= cnt) return;
    int base = d_offsets[e];
    int jn0  = blockIdx.x * 64;

    int tid  = threadIdx.x;
    int lane = tid & 31;
    int wid  = tid >> 5;
    int wm   = wid >> 1;          // 0..3
    int wn   = wid & 1;           // 0..1
    int lm   = lane & 15;
    int lq   = lane >> 4;

    if (tid < BM) {
        int rr = row0 + tid;
        rows_s[tid] = d_row_token[base + ((rr < cnt) ? rr : (cnt - 1))];
    }
    __syncthreads();

    const f16* w1h = d_w1h + (size_t)e * DDIM * 2 * HID;

    float accV[2][4][4], accG[2][4][4];
#pragma unroll
    for (int a = 0; a < 2; a++)
#pragma unroll
        for (int b = 0; b < 4; b++)
#pragma unroll
            for (int c = 0; c < 4; c++) { accV[a][b][c] = 0.f; accG[a][b][c] = 0.f; }

#define G1_LOAD(st, k0)                                                          \
    {                                                                            \
        f16* Ah = S + (st) * G1_STG;                                             \
        f16* Bvh = Ah + A_ELE;                                                   \
        f16* Bgh = Bvh + B1_ELE;                                                 \
        _Pragma("unroll")                                                        \
        for (int i = 0; i < 4; i++) {                                            \
            int id = tid + i * 256;                                              \
            int r = id >> 3, c = (id & 7) * 8;                                   \
            size_t go = (size_t)rows_s[r] * DDIM + (k0) + c;                     \
            cpa16(smem_u32(Ah + r * APAD + c), d_xph + go);                      \
        }                                                                        \
        _Pragma("unroll")                                                        \
        for (int i = 0; i < 2; i++) {                                            \
            int id = tid + i * 256;                                              \
            int kk = id >> 3, c = (id & 7) * 8;                                  \
            size_t gv = (size_t)((k0) + kk) * (2 * HID) + jn0 + c;               \
            cpa16(smem_u32(Bvh + kk * B1PAD + c), w1h + gv);                     \
            cpa16(smem_u32(Bgh + kk * B1PAD + c), w1h + gv + HID);               \
        }                                                                        \
    }

    G1_LOAD(0, 0);
    cpa_commit();

    for (int ch = 0; ch < DDIM / BK; ch++) {
        if (ch + 1 < DDIM / BK) {
            G1_LOAD((ch + 1) & 1, (ch + 1) * BK);
            cpa_commit();
            cpa_wait<1>();
        } else {
            cpa_wait<0>();
        }
        __syncthreads();

        f16* Ah = S + (ch & 1) * G1_STG;
        f16* Bvh = Ah + A_ELE;
        f16* Bgh = Bvh + B1_ELE;

#pragma unroll
        for (int s = 0; s < 4; s++) {
            uint32_t ah[2][4];
#pragma unroll
            for (int tm = 0; tm < 2; tm++) {
                int ro = (wm * 32 + tm * 16 + lm) * APAD + s * 16 + lq * 8;
                ldsm4(ah[tm], smem_u32(Ah + ro));
            }
            uint32_t bvh[2][4], bgh[2][4];
#pragma unroll
            for (int nt = 0; nt < 2; nt++) {
                int bo = (s * 16 + lm) * B1PAD + wn * 32 + nt * 16 + lq * 8;
                ldsm4t(bvh[nt], smem_u32(Bvh + bo));
                ldsm4t(bgh[nt], smem_u32(Bgh + bo));
            }
#pragma unroll
            for (int tm = 0; tm < 2; tm++) {
#pragma unroll
                for (int j = 0; j < 4; j++) {
                    int nt = j >> 1, o = (j & 1) * 2;
                    mma_f16(accV[tm][j], ah[tm], &bvh[nt][o]);
                    mma_f16(accG[tm][j], ah[tm], &bgh[nt][o]);
                }
            }
        }
        __syncthreads();
    }

    // epilogue: SwiGLU -> fp16 he
    int qr = lane >> 2, qc = lane & 3;
#pragma unroll
    for (int tm = 0; tm < 2; tm++) {
#pragma unroll
        for (int p = 0; p < 2; p++) {
            int rl = wm * 32 + tm * 16 + qr + p * 8;
            int r  = row0 + rl;
            if (r >= cnt) continue;
            size_t ho = (size_t)(base + r) * HID;
#pragma unroll
            for (int j = 0; j < 4; j++) {
                float v0 = accV[tm][j][p * 2], v1 = accV[tm][j][p * 2 + 1];
                float g0 = accG[tm][j][p * 2], g1 = accG[tm][j][p * 2 + 1];
                float o0 = v0 / (1.f + expf(-g0));
                float o1 = v1 / (1.f + expf(-g1));
                int col = jn0 + wn * 32 + j * 8 + qc * 2;
                *(f162*)&d_heh[ho + col] = __floats2half2_rn(o0, o1);
            }
        }
    }
}

// ---------------- GEMM2 (launch 5): 128x128, BK=64, gated --------------------
#define G2_STG (A_ELE + B2_ELE)            // 17920 elems / stage
#define G2_SMEM (2 * G2_STG * 2)           // 71680 B
__global__ void __launch_bounds__(256) gemm2_kernel() {
    extern __shared__ f16 S[];
    __shared__ float gate_s[BM];

    int e    = blockIdx.z;
    int cnt  = d_counts[e];
    int row0 = blockIdx.y * BM;
    if (row0 >= cnt) return;
    int base = d_offsets[e];
    int n0   = blockIdx.x * 128;

    int tid  = threadIdx.x;
    int lane = tid & 31;
    int wid  = tid >> 5;
    int wm   = wid >> 1;          // 0..3 (32 rows each)
    int wn   = wid & 1;           // 0..1 (64 cols each)
    int lm   = lane & 15;
    int lq   = lane >> 4;

    if (tid < BM) {
        int rr = row0 + tid;
        gate_s[tid] = (rr < cnt) ? d_row_gate[base + rr] : 0.f;
    }
    __syncthreads();

    const f16* w2h = d_w2h + (size_t)e * HID * DDIM;

    float acc[2][8][4];
#pragma unroll
    for (int a = 0; a < 2; a++)
#pragma unroll
        for (int b = 0; b < 8; b++)
#pragma unroll
            for (int c = 0; c < 4; c++) acc[a][b][c] = 0.f;

#define G2_LOAD(st, k0)                                                          \
    {                                                                            \
        f16* Ah = S + (st) * G2_STG;                                             \
        f16* Bh = Ah + A_ELE;                                                    \
        _Pragma("unroll")                                                        \
        for (int i = 0; i < 4; i++) {                                            \
            int id = tid + i * 256;                                              \
            int r = id >> 3, c = (id & 7) * 8;                                   \
            int rr = row0 + r; if (rr >= cnt) rr = cnt - 1;                      \
            size_t go = (size_t)(base + rr) * HID + (k0) + c;                    \
            cpa16(smem_u32(Ah + r * APAD + c), d_heh + go);                      \
        }                                                                        \
        _Pragma("unroll")                                                        \
        for (int i = 0; i < 4; i++) {                                            \
            int id = tid + i * 256;                                              \
            int kk = id >> 4, c = (id & 15) * 8;                                 \
            size_t gb = (size_t)((k0) + kk) * DDIM + n0 + c;                     \
            cpa16(smem_u32(Bh + kk * B2PAD + c), w2h + gb);                      \
        }                                                                        \
    }

    G2_LOAD(0, 0);
    cpa_commit();

    for (int ch = 0; ch < HID / BK; ch++) {
        if (ch + 1 < HID / BK) {
            G2_LOAD((ch + 1) & 1, (ch + 1) * BK);
            cpa_commit();
            cpa_wait<1>();
        } else {
            cpa_wait<0>();
        }
        __syncthreads();

        f16* Ah = S + (ch & 1) * G2_STG;
        f16* Bh = Ah + A_ELE;

#pragma unroll
        for (int s = 0; s < 4; s++) {
            uint32_t ah[2][4];
#pragma unroll
            for (int tm = 0; tm < 2; tm++) {
                int ro = (wm * 32 + tm * 16 + lm) * APAD + s * 16 + lq * 8;
                ldsm4(ah[tm], smem_u32(Ah + ro));
            }
            uint32_t bh[4][4];
#pragma unroll
            for (int nt = 0; nt < 4; nt++) {
                int bo = (s * 16 + lm) * B2PAD + wn * 64 + nt * 16 + lq * 8;
                ldsm4t(bh[nt], smem_u32(Bh + bo));
            }
#pragma unroll
            for (int tm = 0; tm < 2; tm++) {
#pragma unroll
                for (int j = 0; j < 8; j++) {
                    int nt = j >> 1, o = (j & 1) * 2;
                    mma_f16(acc[tm][j], ah[tm], &bh[nt][o]);
                }
            }
        }
        __syncthreads();
    }

    int qr = lane >> 2, qc = lane & 3;
#pragma unroll
    for (int tm = 0; tm < 2; tm++) {
#pragma unroll
        for (int p = 0; p < 2; p++) {
            int rl = wm * 32 + tm * 16 + qr + p * 8;
            int r  = row0 + rl;
            if (r >= cnt) continue;
            float g = gate_s[rl];
            size_t po = (size_t)(base + r) * DDIM;
#pragma unroll
            for (int j = 0; j < 8; j++) {
                int col = n0 + wn * 64 + j * 8 + qc * 2;
                float2 o = make_float2(g * acc[tm][j][p * 2], g * acc[tm][j][p * 2 + 1]);
                *(float2*)&d_po[po + col] = o;
            }
        }
    }
}

// ---------------- combine (launch 6) -----------------------------------------
__global__ void combine_kernel(float* __restrict__ y) {
    int idx = blockIdx.x * blockDim.x + threadIdx.x;
    if (idx >= NTOK * DDIM) return;
    int w = idx & 31;
    int h = (idx >> 5) & 31;
    int c = (idx >> 10) & 127;
    int b = idx >> 17;
    int n = (b << 8) + ((h >> 1) << 4) + (w >> 1);
    int d = (c << 2) + ((h & 1) << 1) + (w & 1);
    int pr0 = d_tok_pr[n * 2 + 0];
    int pr1 = d_tok_pr[n * 2 + 1];
    y[idx] = d_po[(size_t)pr0 * DDIM + d] + d_po[(size_t)pr1 * DDIM + d];
}

// ---------------- launch -----------------------------------------------------
extern "C" void kernel_launch(void* const* d_in, const int* in_sizes, int n_in,
                              void* d_out, int out_size) {
    const float* x  = (const float*)d_in[0];
    const float* rw = (const float*)d_in[1];
    const float* w1 = (const float*)d_in[2];
    const float* w2 = (const float*)d_in[3];
    float* y = (float*)d_out;

    cudaFuncSetAttribute(gemm1_kernel, cudaFuncAttributeMaxDynamicSharedMemorySize, G1_SMEM);
    cudaFuncSetAttribute(gemm2_kernel, cudaFuncAttributeMaxDynamicSharedMemorySize, G2_SMEM);

    f16 *w1h, *w2h;
    cudaGetSymbolAddress((void**)&w1h, d_w1h);
    cudaGetSymbolAddress((void**)&w2h, d_w2h);

    convert_w_kernel<<<2048, 256>>>(w1, w2, w1h, w2h);                        // 0 (+reset)
    patchify_kernel<<<(NTOK * DDIM + 255) / 256, 256>>>(x);                   // 1
    router_kernel<<<NTOK / 8, 256>>>(rw);                                     // 2
    scatter_kernel<<<1, 256>>>();                                             // 3
    gemm1_kernel<<<dim3(HID / 64, NTOK / BM, NEXP), 256, G1_SMEM>>>();        // 4
    gemm2_kernel<<<dim3(DDIM / 128, NTOK / BM, NEXP), 256, G2_SMEM>>>();      // 5 (ncu -s5)
    combine_kernel<<<(NTOK * DDIM + 255) / 256, 256>>>(y);                    // 6
}

// round 12
// speedup vs baseline: 6.8548x; 1.2164x over previous
#include <cuda_runtime.h>
#include <cuda_fp16.h>
#include <math.h>
#include <stdint.h>

// Problem constants
#define NTOK 4096
#define DDIM 512
#define NEXP 8
#define HID  1024
#define NPAIR (NTOK * 2)
#define CC   128
#define HH   32
#define WW   32

typedef __half  f16;
typedef __half2 f162;

// ---------------- static device scratch --------------------------------------
__device__ float d_xp [NTOK * DDIM];                     // fp32 tokens (router)
__device__ __align__(256) f16 d_xph[NTOK * DDIM];        // fp16 tokens (GEMM1 A)
__device__ __align__(256) f16 d_heh[NPAIR * HID];        // fp16 swiglu acts (GEMM2 A)
__device__ float d_po [NPAIR * DDIM];                    // gate-scaled outputs
__device__ __align__(256) f16 d_w1h[NEXP * DDIM * 2 * HID];  // w1 fp16
__device__ __align__(256) f16 d_w2h[NEXP * HID * DDIM];      // w2 fp16
__device__ int   d_counts[NEXP];
__device__ int   d_offsets[NEXP];
__device__ int   d_tok_e[NTOK * 2];
__device__ int   d_tok_r[NTOK * 2];
__device__ float d_tok_g[NTOK * 2];
__device__ int   d_tok_pr[NTOK * 2];
__device__ int   d_row_token[NPAIR];
__device__ float d_row_gate[NPAIR];

// ---------------- helpers -----------------------------------------------------
__device__ __forceinline__ uint32_t smem_u32(const void* p) {
    return (uint32_t)__cvta_generic_to_shared(p);
}
__device__ __forceinline__ void ldsm4(uint32_t* r, uint32_t addr) {
    asm volatile("ldmatrix.sync.aligned.m8n8.x4.shared.b16 {%0,%1,%2,%3}, [%4];"
                 : "=r"(r[0]), "=r"(r[1]), "=r"(r[2]), "=r"(r[3]) : "r"(addr));
}
__device__ __forceinline__ void ldsm4t(uint32_t* r, uint32_t addr) {
    asm volatile("ldmatrix.sync.aligned.m8n8.x4.trans.shared.b16 {%0,%1,%2,%3}, [%4];"
                 : "=r"(r[0]), "=r"(r[1]), "=r"(r[2]), "=r"(r[3]) : "r"(addr));
}
__device__ __forceinline__ void mma_f16(float* d, const uint32_t* a, const uint32_t* b) {
    asm volatile(
        "mma.sync.aligned.m16n8k16.row.col.f32.f16.f16.f32 "
        "{%0,%1,%2,%3}, {%4,%5,%6,%7}, {%8,%9}, {%0,%1,%2,%3};"
        : "+f"(d[0]), "+f"(d[1]), "+f"(d[2]), "+f"(d[3])
        : "r"(a[0]), "r"(a[1]), "r"(a[2]), "r"(a[3]), "r"(b[0]), "r"(b[1]));
}
__device__ __forceinline__ void cpa16(uint32_t dst, const void* src) {
    asm volatile("cp.async.cg.shared.global [%0], [%1], 16;" :: "r"(dst), "l"(src));
}
__device__ __forceinline__ void cpa_commit() {
    asm volatile("cp.async.commit_group;" ::: "memory");
}
template<int N> __device__ __forceinline__ void cpa_wait() {
    asm volatile("cp.async.wait_group %0;" :: "n"(N) : "memory");
}

// Tile geometry
#define BM    128
#define BK    64
#define APAD  72     // 64 + 8 halves (144B row stride: conflict-free ldsm)
#define B1PAD 72     // G1 B: 64-wide + 8
#define B2PAD 136    // G2 B: 128-wide + 8
#define A_ELE  (BM * APAD)        // 9216
#define B1_ELE (BK * B1PAD)       // 4608
#define B2_ELE (BK * B2PAD)       // 8704

// ---------------- weight cast + reset (launch 0), vectorized ------------------
__global__ void convert_w_kernel(const float* __restrict__ w1,
                                 const float* __restrict__ w2,
                                 f16* __restrict__ w1h, f16* __restrict__ w2h) {
    const int v1 = (NEXP * DDIM * 2 * HID) / 4;   // float4 count in w1
    const int v2 = (NEXP * HID * DDIM) / 4;
    if (blockIdx.x == 0 && threadIdx.x < NEXP) d_counts[threadIdx.x] = 0;
    int i = blockIdx.x * blockDim.x + threadIdx.x;
    int stride = gridDim.x * blockDim.x;
    for (; i < v1 + v2; i += stride) {
        const float4* src; f16* dst; int j;
        if (i < v1) { src = (const float4*)w1; dst = w1h; j = i; }
        else        { src = (const float4*)w2; dst = w2h; j = i - v1; }
        float4 v = src[j];
        f162 lo = __floats2half2_rn(v.x, v.y);
        f162 hi = __floats2half2_rn(v.z, v.w);
        uint2 pk = make_uint2(*(uint32_t*)&lo, *(uint32_t*)&hi);
        *(uint2*)(dst + j * 4) = pk;
    }
}

// ---------------- patchify (launch 1): thread per (token, channel) ------------
__global__ void patchify_kernel(const float* __restrict__ x) {
    int idx = blockIdx.x * blockDim.x + threadIdx.x;    // NTOK * CC threads
    if (idx >= NTOK * CC) return;
    int n = idx >> 7;            // token
    int c = idx & 127;
    int b  = n >> 8;
    int h2 = (n >> 4) & 15;
    int w2 = n & 15;
    size_t xo = ((size_t)(b * CC + c) * HH + h2 * 2) * WW + w2 * 2;
    float2 v0 = *(const float2*)(x + xo);          // ph=0: pw 0,1
    float2 v1 = *(const float2*)(x + xo + WW);     // ph=1: pw 0,1
    size_t po = (size_t)n * DDIM + c * 4;
    *(float4*)(d_xp + po) = make_float4(v0.x, v0.y, v1.x, v1.y);
    f162 lo = __floats2half2_rn(v0.x, v0.y);
    f162 hi = __floats2half2_rn(v1.x, v1.y);
    *(uint2*)(d_xph + po) = make_uint2(*(uint32_t*)&lo, *(uint32_t*)&hi);
}

// ---------------- router (launch 2) ------------------------------------------
__global__ void router_kernel(const float* __restrict__ rw) {
    __shared__ float rwT[NEXP * DDIM];
    int tid = threadIdx.x;
    for (int i = tid; i < NEXP * DDIM; i += blockDim.x) {
        int k = i >> 3, e = i & 7;
        rwT[e * DDIM + k] = rw[i];
    }
    __syncthreads();

    int warp = tid >> 5, lane = tid & 31;
    int n = blockIdx.x * 8 + warp;
    if (n >= NTOK) return;

    const float* xr = d_xp + (size_t)n * DDIM;
    float acc[NEXP];
#pragma unroll
    for (int e = 0; e < NEXP; e++) acc[e] = 0.f;
#pragma unroll
    for (int t = 0; t < DDIM / 32; t++) {
        int k = lane + t * 32;
        float xv = xr[k];
#pragma unroll
        for (int e = 0; e < NEXP; e++) acc[e] += xv * rwT[e * DDIM + k];
    }
#pragma unroll
    for (int e = 0; e < NEXP; e++) {
#pragma unroll
        for (int off = 16; off > 0; off >>= 1)
            acc[e] += __shfl_xor_sync(0xFFFFFFFFu, acc[e], off);
    }
    if (lane == 0) {
        int i0 = 0; float l0 = acc[0];
#pragma unroll
        for (int e = 1; e < NEXP; e++) if (acc[e] > l0) { l0 = acc[e]; i0 = e; }
        int i1 = -1; float l1 = -1e30f;
#pragma unroll
        for (int e = 0; e < NEXP; e++) if (e != i0 && acc[e] > l1) { l1 = acc[e]; i1 = e; }
        float g0 = 1.f / (1.f + expf(l1 - l0));
        float g1 = 1.f - g0;
        int r0 = atomicAdd(&d_counts[i0], 1);
        int r1 = atomicAdd(&d_counts[i1], 1);
        d_tok_e[n * 2 + 0] = i0; d_tok_r[n * 2 + 0] = r0; d_tok_g[n * 2 + 0] = g0;
        d_tok_e[n * 2 + 1] = i1; d_tok_r[n * 2 + 1] = r1; d_tok_g[n * 2 + 1] = g1;
    }
}

// ---------------- offsets (launch 3) ------------------------------------------
__global__ void offsets_kernel() {
    int s = 0;
    for (int e = 0; e < NEXP; e++) { d_offsets[e] = s; s += d_counts[e]; }
}

// ---------------- scatter (launch 4): parallel --------------------------------
__global__ void scatter_kernel() {
    int n = blockIdx.x * blockDim.x + threadIdx.x;
    if (n >= NTOK) return;
#pragma unroll
    for (int j = 0; j < 2; j++) {
        int e = d_tok_e[n * 2 + j];
        int pr = d_offsets[e] + d_tok_r[n * 2 + j];
        d_row_token[pr] = n;
        d_row_gate[pr]  = d_tok_g[n * 2 + j];
        d_tok_pr[n * 2 + j] = pr;
    }
}

// ---------------- GEMM1 (launch 5): 128x(64v+64g), BK=64, fused SwiGLU -------
#define G1_STG (A_ELE + 2 * B1_ELE)        // 18432 elems / stage
#define G1_SMEM (2 * G1_STG * 2)           // 73728 B
__global__ void __launch_bounds__(256) gemm1_kernel() {
    extern __shared__ f16 S[];
    __shared__ int rows_s[BM];

    int e    = blockIdx.z;
    int cnt  = d_counts[e];
    int row0 = blockIdx.y * BM;
    if (row0 >= cnt) return;
    int base = d_offsets[e];
    int jn0  = blockIdx.x * 64;

    int tid  = threadIdx.x;
    int lane = tid & 31;
    int wid  = tid >> 5;
    int wm   = wid >> 1;          // 0..3
    int wn   = wid & 1;           // 0..1
    int lm   = lane & 15;
    int lq   = lane >> 4;

    if (tid < BM) {
        int rr = row0 + tid;
        rows_s[tid] = d_row_token[base + ((rr < cnt) ? rr : (cnt - 1))];
    }
    __syncthreads();

    const f16* w1h = d_w1h + (size_t)e * DDIM * 2 * HID;

    float accV[2][4][4], accG[2][4][4];
#pragma unroll
    for (int a = 0; a < 2; a++)
#pragma unroll
        for (int b = 0; b < 4; b++)
#pragma unroll
            for (int c = 0; c < 4; c++) { accV[a][b][c] = 0.f; accG[a][b][c] = 0.f; }

#define G1_LOAD(st, k0)                                                          \
    {                                                                            \
        f16* Ah = S + (st) * G1_STG;                                             \
        f16* Bvh = Ah + A_ELE;                                                   \
        f16* Bgh = Bvh + B1_ELE;                                                 \
        _Pragma("unroll")                                                        \
        for (int i = 0; i < 4; i++) {                                            \
            int id = tid + i * 256;                                              \
            int r = id >> 3, c = (id & 7) * 8;                                   \
            size_t go = (size_t)rows_s[r] * DDIM + (k0) + c;                     \
            cpa16(smem_u32(Ah + r * APAD + c), d_xph + go);                      \
        }                                                                        \
        _Pragma("unroll")                                                        \
        for (int i = 0; i < 2; i++) {                                            \
            int id = tid + i * 256;                                              \
            int kk = id >> 3, c = (id & 7) * 8;                                  \
            size_t gv = (size_t)((k0) + kk) * (2 * HID) + jn0 + c;               \
            cpa16(smem_u32(Bvh + kk * B1PAD + c), w1h + gv);                     \
            cpa16(smem_u32(Bgh + kk * B1PAD + c), w1h + gv + HID);               \
        }                                                                        \
    }

    G1_LOAD(0, 0);
    cpa_commit();

    for (int ch = 0; ch < DDIM / BK; ch++) {
        if (ch + 1 < DDIM / BK) {
            G1_LOAD((ch + 1) & 1, (ch + 1) * BK);
            cpa_commit();
            cpa_wait<1>();
        } else {
            cpa_wait<0>();
        }
        __syncthreads();

        f16* Ah = S + (ch & 1) * G1_STG;
        f16* Bvh = Ah + A_ELE;
        f16* Bgh = Bvh + B1_ELE;

#pragma unroll
        for (int s = 0; s < 4; s++) {
            uint32_t ah[2][4];
#pragma unroll
            for (int tm = 0; tm < 2; tm++) {
                int ro = (wm * 32 + tm * 16 + lm) * APAD + s * 16 + lq * 8;
                ldsm4(ah[tm], smem_u32(Ah + ro));
            }
            uint32_t bvh[2][4], bgh[2][4];
#pragma unroll
            for (int nt = 0; nt < 2; nt++) {
                int bo = (s * 16 + lm) * B1PAD + wn * 32 + nt * 16 + lq * 8;
                ldsm4t(bvh[nt], smem_u32(Bvh + bo));
                ldsm4t(bgh[nt], smem_u32(Bgh + bo));
            }
#pragma unroll
            for (int tm = 0; tm < 2; tm++) {
#pragma unroll
                for (int j = 0; j < 4; j++) {
                    int nt = j >> 1, o = (j & 1) * 2;
                    mma_f16(accV[tm][j], ah[tm], &bvh[nt][o]);
                    mma_f16(accG[tm][j], ah[tm], &bgh[nt][o]);
                }
            }
        }
        __syncthreads();
    }

    // epilogue: SwiGLU -> fp16 he
    int qr = lane >> 2, qc = lane & 3;
#pragma unroll
    for (int tm = 0; tm < 2; tm++) {
#pragma unroll
        for (int p = 0; p < 2; p++) {
            int rl = wm * 32 + tm * 16 + qr + p * 8;
            int r  = row0 + rl;
            if (r >= cnt) continue;
            size_t ho = (size_t)(base + r) * HID;
#pragma unroll
            for (int j = 0; j < 4; j++) {
                float v0 = accV[tm][j][p * 2], v1 = accV[tm][j][p * 2 + 1];
                float g0 = accG[tm][j][p * 2], g1 = accG[tm][j][p * 2 + 1];
                float o0 = v0 / (1.f + expf(-g0));
                float o1 = v1 / (1.f + expf(-g1));
                int col = jn0 + wn * 32 + j * 8 + qc * 2;
                *(f162*)&d_heh[ho + col] = __floats2half2_rn(o0, o1);
            }
        }
    }
}

// ---------------- GEMM2 (launch 6): 128x128, BK=64, gated --------------------
#define G2_STG (A_ELE + B2_ELE)            // 17920 elems / stage
#define G2_SMEM (2 * G2_STG * 2)           // 71680 B
__global__ void __launch_bounds__(256) gemm2_kernel() {
    extern __shared__ f16 S[];
    __shared__ float gate_s[BM];

    int e    = blockIdx.z;
    int cnt  = d_counts[e];
    int row0 = blockIdx.y * BM;
    if (row0 >= cnt) return;
    int base = d_offsets[e];
    int n0   = blockIdx.x * 128;

    int tid  = threadIdx.x;
    int lane = tid & 31;
    int wid  = tid >> 5;
    int wm   = wid >> 1;          // 0..3 (32 rows each)
    int wn   = wid & 1;           // 0..1 (64 cols each)
    int lm   = lane & 15;
    int lq   = lane >> 4;

    if (tid < BM) {
        int rr = row0 + tid;
        gate_s[tid] = (rr < cnt) ? d_row_gate[base + rr] : 0.f;
    }
    __syncthreads();

    const f16* w2h = d_w2h + (size_t)e * HID * DDIM;

    float acc[2][8][4];
#pragma unroll
    for (int a = 0; a < 2; a++)
#pragma unroll
        for (int b = 0; b < 8; b++)
#pragma unroll
            for (int c = 0; c < 4; c++) acc[a][b][c] = 0.f;

#define G2_LOAD(st, k0)                                                          \
    {                                                                            \
        f16* Ah = S + (st) * G2_STG;                                             \
        f16* Bh = Ah + A_ELE;                                                    \
        _Pragma("unroll")                                                        \
        for (int i = 0; i < 4; i++) {                                            \
            int id = tid + i * 256;                                              \
            int r = id >> 3, c = (id & 7) * 8;                                   \
            int rr = row0 + r; if (rr >= cnt) rr = cnt - 1;                      \
            size_t go = (size_t)(base + rr) * HID + (k0) + c;                    \
            cpa16(smem_u32(Ah + r * APAD + c), d_heh + go);                      \
        }                                                                        \
        _Pragma("unroll")                                                        \
        for (int i = 0; i < 4; i++) {                                            \
            int id = tid + i * 256;                                              \
            int kk = id >> 4, c = (id & 15) * 8;                                 \
            size_t gb = (size_t)((k0) + kk) * DDIM + n0 + c;                     \
            cpa16(smem_u32(Bh + kk * B2PAD + c), w2h + gb);                      \
        }                                                                        \
    }

    G2_LOAD(0, 0);
    cpa_commit();

    for (int ch = 0; ch < HID / BK; ch++) {
        if (ch + 1 < HID / BK) {
            G2_LOAD((ch + 1) & 1, (ch + 1) * BK);
            cpa_commit();
            cpa_wait<1>();
        } else {
            cpa_wait<0>();
        }
        __syncthreads();

        f16* Ah = S + (ch & 1) * G2_STG;
        f16* Bh = Ah + A_ELE;

#pragma unroll
        for (int s = 0; s < 4; s++) {
            uint32_t ah[2][4];
#pragma unroll
            for (int tm = 0; tm < 2; tm++) {
                int ro = (wm * 32 + tm * 16 + lm) * APAD + s * 16 + lq * 8;
                ldsm4(ah[tm], smem_u32(Ah + ro));
            }
            uint32_t bh[4][4];
#pragma unroll
            for (int nt = 0; nt < 4; nt++) {
                int bo = (s * 16 + lm) * B2PAD + wn * 64 + nt * 16 + lq * 8;
                ldsm4t(bh[nt], smem_u32(Bh + bo));
            }
#pragma unroll
            for (int tm = 0; tm < 2; tm++) {
#pragma unroll
                for (int j = 0; j < 8; j++) {
                    int nt = j >> 1, o = (j & 1) * 2;
                    mma_f16(acc[tm][j], ah[tm], &bh[nt][o]);
                }
            }
        }
        __syncthreads();
    }

    int qr = lane >> 2, qc = lane & 3;
#pragma unroll
    for (int tm = 0; tm < 2; tm++) {
#pragma unroll
        for (int p = 0; p < 2; p++) {
            int rl = wm * 32 + tm * 16 + qr + p * 8;
            int r  = row0 + rl;
            if (r >= cnt) continue;
            float g = gate_s[rl];
            size_t po = (size_t)(base + r) * DDIM;
#pragma unroll
            for (int j = 0; j < 8; j++) {
                int col = n0 + wn * 64 + j * 8 + qc * 2;
                float2 o = make_float2(g * acc[tm][j][p * 2], g * acc[tm][j][p * 2 + 1]);
                *(float2*)&d_po[po + col] = o;
            }
        }
    }
}

// ---------------- combine (launch 7): float2 per thread -----------------------
__global__ void combine_kernel(float* __restrict__ y) {
    int idx = blockIdx.x * blockDim.x + threadIdx.x;    // NTOK*DDIM/2 threads
    if (idx >= NTOK * DDIM / 2) return;
    // idx -> (b, c, h, w2): w2 fastest (16), then h (32), then c (128), then b
    int w2 = idx & 15;
    int h  = (idx >> 4) & 31;
    int c  = (idx >> 9) & 127;
    int b  = idx >> 16;
    int n  = (b << 8) + ((h >> 1) << 4) + w2;
    int d0 = (c << 2) + ((h & 1) << 1);                 // pw 0,1 contiguous
    int pr0 = d_tok_pr[n * 2 + 0];
    int pr1 = d_tok_pr[n * 2 + 1];
    float2 a = *(const float2*)&d_po[(size_t)pr0 * DDIM + d0];
    float2 bb = *(const float2*)&d_po[(size_t)pr1 * DDIM + d0];
    size_t yo = ((size_t)(b * CC + c) * HH + h) * WW + w2 * 2;
    *(float2*)(y + yo) = make_float2(a.x + bb.x, a.y + bb.y);
}

// ---------------- launch -----------------------------------------------------
extern "C" void kernel_launch(void* const* d_in, const int* in_sizes, int n_in,
                              void* d_out, int out_size) {
    const float* x  = (const float*)d_in[0];
    const float* rw = (const float*)d_in[1];
    const float* w1 = (const float*)d_in[2];
    const float* w2 = (const float*)d_in[3];
    float* y = (float*)d_out;

    cudaFuncSetAttribute(gemm1_kernel, cudaFuncAttributeMaxDynamicSharedMemorySize, G1_SMEM);
    cudaFuncSetAttribute(gemm2_kernel, cudaFuncAttributeMaxDynamicSharedMemorySize, G2_SMEM);

    f16 *w1h, *w2h;
    cudaGetSymbolAddress((void**)&w1h, d_w1h);
    cudaGetSymbolAddress((void**)&w2h, d_w2h);

    convert_w_kernel<<<1024, 256>>>(w1, w2, w1h, w2h);                        // 0 (+reset)
    patchify_kernel<<<(NTOK * CC + 255) / 256, 256>>>(x);                     // 1
    router_kernel<<<NTOK / 8, 256>>>(rw);                                     // 2
    offsets_kernel<<<1, 1>>>();                                               // 3
    scatter_kernel<<<(NTOK + 255) / 256, 256>>>();                            // 4
    gemm1_kernel<<<dim3(HID / 64, NTOK / BM, NEXP), 256, G1_SMEM>>>();        // 5 (ncu -s5)
    gemm2_kernel<<<dim3(DDIM / 128, NTOK / BM, NEXP), 256, G2_SMEM>>>();      // 6
    combine_kernel<<<(NTOK * DDIM / 2 + 255) / 256, 256>>>(y);                // 7
}

// round 13
// speedup vs baseline: 6.9448x; 1.0131x over previous
#include <cuda_runtime.h>
#include <cuda_fp16.h>
#include <math.h>
#include <stdint.h>

// Problem constants
#define NTOK 4096
#define DDIM 512
#define NEXP 8
#define HID  1024
#define NPAIR (NTOK * 2)
#define CC   128
#define HH   32
#define WW   32

typedef __half  f16;
typedef __half2 f162;

// ---------------- static device scratch --------------------------------------
__device__ __align__(256) f16 d_xph[NTOK * DDIM];        // fp16 tokens (GEMM1 A)
__device__ __align__(256) f16 d_heh[NPAIR * HID];        // fp16 swiglu acts (GEMM2 A)
__device__ float d_po [NPAIR * DDIM];                    // gate-scaled outputs
__device__ __align__(256) f16 d_w1h[NEXP * DDIM * 2 * HID];  // w1 fp16
__device__ __align__(256) f16 d_w2h[NEXP * HID * DDIM];      // w2 fp16
__device__ int   d_counts[NEXP];
__device__ int   d_offsets[NEXP];
__device__ int   d_tok_e[NTOK * 2];
__device__ int   d_tok_r[NTOK * 2];
__device__ float d_tok_g[NTOK * 2];
__device__ int   d_tok_pr[NTOK * 2];
__device__ int   d_row_token[NPAIR];
__device__ float d_row_gate[NPAIR];

// ---------------- helpers -----------------------------------------------------
__device__ __forceinline__ uint32_t smem_u32(const void* p) {
    return (uint32_t)__cvta_generic_to_shared(p);
}
__device__ __forceinline__ void ldsm4(uint32_t* r, uint32_t addr) {
    asm volatile("ldmatrix.sync.aligned.m8n8.x4.shared.b16 {%0,%1,%2,%3}, [%4];"
                 : "=r"(r[0]), "=r"(r[1]), "=r"(r[2]), "=r"(r[3]) : "r"(addr));
}
__device__ __forceinline__ void ldsm4t(uint32_t* r, uint32_t addr) {
    asm volatile("ldmatrix.sync.aligned.m8n8.x4.trans.shared.b16 {%0,%1,%2,%3}, [%4];"
                 : "=r"(r[0]), "=r"(r[1]), "=r"(r[2]), "=r"(r[3]) : "r"(addr));
}
__device__ __forceinline__ void mma_f16(float* d, const uint32_t* a, const uint32_t* b) {
    asm volatile(
        "mma.sync.aligned.m16n8k16.row.col.f32.f16.f16.f32 "
        "{%0,%1,%2,%3}, {%4,%5,%6,%7}, {%8,%9}, {%0,%1,%2,%3};"
        : "+f"(d[0]), "+f"(d[1]), "+f"(d[2]), "+f"(d[3])
        : "r"(a[0]), "r"(a[1]), "r"(a[2]), "r"(a[3]), "r"(b[0]), "r"(b[1]));
}
__device__ __forceinline__ void cpa16(uint32_t dst, const void* src) {
    asm volatile("cp.async.cg.shared.global [%0], [%1], 16;" :: "r"(dst), "l"(src));
}
__device__ __forceinline__ void cpa_commit() {
    asm volatile("cp.async.commit_group;" ::: "memory");
}
template<int N> __device__ __forceinline__ void cpa_wait() {
    asm volatile("cp.async.wait_group %0;" :: "n"(N) : "memory");
}

// Tile geometry
#define BM    128
#define BK    64
#define APAD  72     // 64 + 8 halves (144B row stride: conflict-free ldsm)
#define B1PAD 72     // G1 B: 64-wide + 8
#define B2PAD 136    // G2 B: 128-wide + 8
#define A_ELE  (BM * APAD)        // 9216
#define B1_ELE (BK * B1PAD)       // 4608
#define B2_ELE (BK * B2PAD)       // 8704

// ---------------- weight cast + reset (launch 0), vectorized ------------------
__global__ void convert_w_kernel(const float* __restrict__ w1,
                                 const float* __restrict__ w2,
                                 f16* __restrict__ w1h, f16* __restrict__ w2h) {
    const int v1 = (NEXP * DDIM * 2 * HID) / 4;   // float4 count in w1
    const int v2 = (NEXP * HID * DDIM) / 4;
    if (blockIdx.x == 0 && threadIdx.x < NEXP) d_counts[threadIdx.x] = 0;
    int i = blockIdx.x * blockDim.x + threadIdx.x;
    int stride = gridDim.x * blockDim.x;
    for (; i < v1 + v2; i += stride) {
        const float4* src; f16* dst; int j;
        if (i < v1) { src = (const float4*)w1; dst = w1h; j = i; }
        else        { src = (const float4*)w2; dst = w2h; j = i - v1; }
        float4 v = src[j];
        f162 lo = __floats2half2_rn(v.x, v.y);
        f162 hi = __floats2half2_rn(v.z, v.w);
        uint2 pk = make_uint2(*(uint32_t*)&lo, *(uint32_t*)&hi);
        *(uint2*)(dst + j * 4) = pk;
    }
}

// ---------------- patchify + router merged (launch 1) -------------------------
// Block = 256 threads, 8 tokens. Patchify into smem + d_xph, logits from smem.
__global__ void __launch_bounds__(256) router_kernel(const float* __restrict__ x,
                                                     const float* __restrict__ rw) {
    __shared__ float rwT[NEXP * DDIM];    // rwT[e*512+k], 16KB
    __shared__ float xs[8][DDIM];         // patchified fp32 tokens, 16KB

    int tid = threadIdx.x;
    int n0  = blockIdx.x * 8;

    for (int i = tid; i < NEXP * DDIM; i += 256) {
        int k = i >> 3, e = i & 7;
        rwT[e * DDIM + k] = rw[i];
    }

    // patchify: unit = (c<<3)|tok  (tok fastest -> coalesced x loads)
#pragma unroll
    for (int i = 0; i < 4; i++) {
        int unit = tid + i * 256;
        int tok = unit & 7;
        int c   = unit >> 3;
        int n = n0 + tok;
        int b  = n >> 8;
        int h2 = (n >> 4) & 15;
        int w2 = n & 15;
        size_t xo = ((size_t)(b * CC + c) * HH + h2 * 2) * WW + w2 * 2;
        float2 v0 = *(const float2*)(x + xo);
        float2 v1 = *(const float2*)(x + xo + WW);
        int d0 = c * 4;
        xs[tok][d0 + 0] = v0.x; xs[tok][d0 + 1] = v0.y;
        xs[tok][d0 + 2] = v1.x; xs[tok][d0 + 3] = v1.y;
        f162 lo = __floats2half2_rn(v0.x, v0.y);
        f162 hi = __floats2half2_rn(v1.x, v1.y);
        *(uint2*)(d_xph + (size_t)n * DDIM + d0) =
            make_uint2(*(uint32_t*)&lo, *(uint32_t*)&hi);
    }
    __syncthreads();

    // logits: warp per token, float4 smem reads
    int warp = tid >> 5, lane = tid & 31;
    int n = n0 + warp;

    float acc[NEXP];
#pragma unroll
    for (int e = 0; e < NEXP; e++) acc[e] = 0.f;
#pragma unroll
    for (int t = 0; t < 4; t++) {
        int k4 = (lane + t * 32) * 4;
        float4 xv = *(const float4*)&xs[warp][k4];
#pragma unroll
        for (int e = 0; e < NEXP; e++) {
            const float4 wv = *(const float4*)&rwT[e * DDIM + k4];
            acc[e] += xv.x * wv.x + xv.y * wv.y + xv.z * wv.z + xv.w * wv.w;
        }
    }
#pragma unroll
    for (int e = 0; e < NEXP; e++) {
#pragma unroll
        for (int off = 16; off > 0; off >>= 1)
            acc[e] += __shfl_xor_sync(0xFFFFFFFFu, acc[e], off);
    }
    if (lane == 0) {
        int i0 = 0; float l0 = acc[0];
#pragma unroll
        for (int e = 1; e < NEXP; e++) if (acc[e] > l0) { l0 = acc[e]; i0 = e; }
        int i1 = -1; float l1 = -1e30f;
#pragma unroll
        for (int e = 0; e < NEXP; e++) if (e != i0 && acc[e] > l1) { l1 = acc[e]; i1 = e; }
        float g0 = 1.f / (1.f + expf(l1 - l0));
        float g1 = 1.f - g0;
        int r0 = atomicAdd(&d_counts[i0], 1);
        int r1 = atomicAdd(&d_counts[i1], 1);
        d_tok_e[n * 2 + 0] = i0; d_tok_r[n * 2 + 0] = r0; d_tok_g[n * 2 + 0] = g0;
        d_tok_e[n * 2 + 1] = i1; d_tok_r[n * 2 + 1] = r1; d_tok_g[n * 2 + 1] = g1;
    }
}

// ---------------- scatter + offsets (launch 2): per-block local prefix --------
__global__ void scatter_kernel() {
    __shared__ int off_s[NEXP];
    int tid = threadIdx.x;
    if (tid == 0) {
        int s = 0;
#pragma unroll
        for (int e = 0; e < NEXP; e++) {
            off_s[e] = s;
            if (blockIdx.x == 0) d_offsets[e] = s;
            s += d_counts[e];
        }
    }
    __syncthreads();
    int n = blockIdx.x * blockDim.x + tid;
    if (n >= NTOK) return;
#pragma unroll
    for (int j = 0; j < 2; j++) {
        int e = d_tok_e[n * 2 + j];
        int pr = off_s[e] + d_tok_r[n * 2 + j];
        d_row_token[pr] = n;
        d_row_gate[pr]  = d_tok_g[n * 2 + j];
        d_tok_pr[n * 2 + j] = pr;
    }
}

// ---------------- GEMM1 (launch 3, ncu window): fused SwiGLU ------------------
#define G1_STG (A_ELE + 2 * B1_ELE)        // 18432 elems / stage
#define G1_SMEM (2 * G1_STG * 2)           // 73728 B
__global__ void __launch_bounds__(256) gemm1_kernel() {
    extern __shared__ f16 S[];
    __shared__ int rows_s[BM];

    int e    = blockIdx.z;
    int cnt  = d_counts[e];
    int row0 = blockIdx.y * BM;
    if (row0 >= cnt) return;
    int base = d_offsets[e];
    int jn0  = blockIdx.x * 64;

    int tid  = threadIdx.x;
    int lane = tid & 31;
    int wid  = tid >> 5;
    int wm   = wid >> 1;          // 0..3
    int wn   = wid & 1;           // 0..1
    int lm   = lane & 15;
    int lq   = lane >> 4;

    if (tid < BM) {
        int rr = row0 + tid;
        rows_s[tid] = d_row_token[base + ((rr < cnt) ? rr : (cnt - 1))];
    }
    __syncthreads();

    const f16* w1h = d_w1h + (size_t)e * DDIM * 2 * HID;

    float accV[2][4][4], accG[2][4][4];
#pragma unroll
    for (int a = 0; a < 2; a++)
#pragma unroll
        for (int b = 0; b < 4; b++)
#pragma unroll
            for (int c = 0; c < 4; c++) { accV[a][b][c] = 0.f; accG[a][b][c] = 0.f; }

#define G1_LOAD(st, k0)                                                          \
    {                                                                            \
        f16* Ah = S + (st) * G1_STG;                                             \
        f16* Bvh = Ah + A_ELE;                                                   \
        f16* Bgh = Bvh + B1_ELE;                                                 \
        _Pragma("unroll")                                                        \
        for (int i = 0; i < 4; i++) {                                            \
            int id = tid + i * 256;                                              \
            int r = id >> 3, c = (id & 7) * 8;                                   \
            size_t go = (size_t)rows_s[r] * DDIM + (k0) + c;                     \
            cpa16(smem_u32(Ah + r * APAD + c), d_xph + go);                      \
        }                                                                        \
        _Pragma("unroll")                                                        \
        for (int i = 0; i < 2; i++) {                                            \
            int id = tid + i * 256;                                              \
            int kk = id >> 3, c = (id & 7) * 8;                                  \
            size_t gv = (size_t)((k0) + kk) * (2 * HID) + jn0 + c;               \
            cpa16(smem_u32(Bvh + kk * B1PAD + c), w1h + gv);                     \
            cpa16(smem_u32(Bgh + kk * B1PAD + c), w1h + gv + HID);               \
        }                                                                        \
    }

    G1_LOAD(0, 0);
    cpa_commit();

    for (int ch = 0; ch < DDIM / BK; ch++) {
        if (ch + 1 < DDIM / BK) {
            G1_LOAD((ch + 1) & 1, (ch + 1) * BK);
            cpa_commit();
            cpa_wait<1>();
        } else {
            cpa_wait<0>();
        }
        __syncthreads();

        f16* Ah = S + (ch & 1) * G1_STG;
        f16* Bvh = Ah + A_ELE;
        f16* Bgh = Bvh + B1_ELE;

#pragma unroll
        for (int s = 0; s < 4; s++) {
            uint32_t ah[2][4];
#pragma unroll
            for (int tm = 0; tm < 2; tm++) {
                int ro = (wm * 32 + tm * 16 + lm) * APAD + s * 16 + lq * 8;
                ldsm4(ah[tm], smem_u32(Ah + ro));
            }
            uint32_t bvh[2][4], bgh[2][4];
#pragma unroll
            for (int nt = 0; nt < 2; nt++) {
                int bo = (s * 16 + lm) * B1PAD + wn * 32 + nt * 16 + lq * 8;
                ldsm4t(bvh[nt], smem_u32(Bvh + bo));
                ldsm4t(bgh[nt], smem_u32(Bgh + bo));
            }
#pragma unroll
            for (int tm = 0; tm < 2; tm++) {
#pragma unroll
                for (int j = 0; j < 4; j++) {
                    int nt = j >> 1, o = (j & 1) * 2;
                    mma_f16(accV[tm][j], ah[tm], &bvh[nt][o]);
                    mma_f16(accG[tm][j], ah[tm], &bgh[nt][o]);
                }
            }
        }
        __syncthreads();
    }

    // epilogue: SwiGLU -> fp16 he
    int qr = lane >> 2, qc = lane & 3;
#pragma unroll
    for (int tm = 0; tm < 2; tm++) {
#pragma unroll
        for (int p = 0; p < 2; p++) {
            int rl = wm * 32 + tm * 16 + qr + p * 8;
            int r  = row0 + rl;
            if (r >= cnt) continue;
            size_t ho = (size_t)(base + r) * HID;
#pragma unroll
            for (int j = 0; j < 4; j++) {
                float v0 = accV[tm][j][p * 2], v1 = accV[tm][j][p * 2 + 1];
                float g0 = accG[tm][j][p * 2], g1 = accG[tm][j][p * 2 + 1];
                float o0 = v0 / (1.f + expf(-g0));
                float o1 = v1 / (1.f + expf(-g1));
                int col = jn0 + wn * 32 + j * 8 + qc * 2;
                *(f162*)&d_heh[ho + col] = __floats2half2_rn(o0, o1);
            }
        }
    }
}

// ---------------- GEMM2 (launch 4): 128x128, BK=64, gated --------------------
#define G2_STG (A_ELE + B2_ELE)            // 17920 elems / stage
#define G2_SMEM (2 * G2_STG * 2)           // 71680 B
__global__ void __launch_bounds__(256) gemm2_kernel() {
    extern __shared__ f16 S[];
    __shared__ float gate_s[BM];

    int e    = blockIdx.z;
    int cnt  = d_counts[e];
    int row0 = blockIdx.y * BM;
    if (row0 >= cnt) return;
    int base = d_offsets[e];
    int n0   = blockIdx.x * 128;

    int tid  = threadIdx.x;
    int lane = tid & 31;
    int wid  = tid >> 5;
    int wm   = wid >> 1;          // 0..3 (32 rows each)
    int wn   = wid & 1;           // 0..1 (64 cols each)
    int lm   = lane & 15;
    int lq   = lane >> 4;

    if (tid < BM) {
        int rr = row0 + tid;
        gate_s[tid] = (rr < cnt) ? d_row_gate[base + rr] : 0.f;
    }
    __syncthreads();

    const f16* w2h = d_w2h + (size_t)e * HID * DDIM;

    float acc[2][8][4];
#pragma unroll
    for (int a = 0; a < 2; a++)
#pragma unroll
        for (int b = 0; b < 8; b++)
#pragma unroll
            for (int c = 0; c < 4; c++) acc[a][b][c] = 0.f;

#define G2_LOAD(st, k0)                                                          \
    {                                                                            \
        f16* Ah = S + (st) * G2_STG;                                             \
        f16* Bh = Ah + A_ELE;                                                    \
        _Pragma("unroll")                                                        \
        for (int i = 0; i < 4; i++) {                                            \
            int id = tid + i * 256;                                              \
            int r = id >> 3, c = (id & 7) * 8;                                   \
            int rr = row0 + r; if (rr >= cnt) rr = cnt - 1;                      \
            size_t go = (size_t)(base + rr) * HID + (k0) + c;                    \
            cpa16(smem_u32(Ah + r * APAD + c), d_heh + go);                      \
        }                                                                        \
        _Pragma("unroll")                                                        \
        for (int i = 0; i < 4; i++) {                                            \
            int id = tid + i * 256;                                              \
            int kk = id >> 4, c = (id & 15) * 8;                                 \
            size_t gb = (size_t)((k0) + kk) * DDIM + n0 + c;                     \
            cpa16(smem_u32(Bh + kk * B2PAD + c), w2h + gb);                      \
        }                                                                        \
    }

    G2_LOAD(0, 0);
    cpa_commit();

    for (int ch = 0; ch < HID / BK; ch++) {
        if (ch + 1 < HID / BK) {
            G2_LOAD((ch + 1) & 1, (ch + 1) * BK);
            cpa_commit();
            cpa_wait<1>();
        } else {
            cpa_wait<0>();
        }
        __syncthreads();

        f16* Ah = S + (ch & 1) * G2_STG;
        f16* Bh = Ah + A_ELE;

#pragma unroll
        for (int s = 0; s < 4; s++) {
            uint32_t ah[2][4];
#pragma unroll
            for (int tm = 0; tm < 2; tm++) {
                int ro = (wm * 32 + tm * 16 + lm) * APAD + s * 16 + lq * 8;
                ldsm4(ah[tm], smem_u32(Ah + ro));
            }
            uint32_t bh[4][4];
#pragma unroll
            for (int nt = 0; nt < 4; nt++) {
                int bo = (s * 16 + lm) * B2PAD + wn * 64 + nt * 16 + lq * 8;
                ldsm4t(bh[nt], smem_u32(Bh + bo));
            }
#pragma unroll
            for (int tm = 0; tm < 2; tm++) {
#pragma unroll
                for (int j = 0; j < 8; j++) {
                    int nt = j >> 1, o = (j & 1) * 2;
                    mma_f16(acc[tm][j], ah[tm], &bh[nt][o]);
                }
            }
        }
        __syncthreads();
    }

    int qr = lane >> 2, qc = lane & 3;
#pragma unroll
    for (int tm = 0; tm < 2; tm++) {
#pragma unroll
        for (int p = 0; p < 2; p++) {
            int rl = wm * 32 + tm * 16 + qr + p * 8;
            int r  = row0 + rl;
            if (r >= cnt) continue;
            float g = gate_s[rl];
            size_t po = (size_t)(base + r) * DDIM;
#pragma unroll
            for (int j = 0; j < 8; j++) {
                int col = n0 + wn * 64 + j * 8 + qc * 2;
                float2 o = make_float2(g * acc[tm][j][p * 2], g * acc[tm][j][p * 2 + 1]);
                *(float2*)&d_po[po + col] = o;
            }
        }
    }
}

// ---------------- combine (launch 5): float2 per thread -----------------------
__global__ void combine_kernel(float* __restrict__ y) {
    int idx = blockIdx.x * blockDim.x + threadIdx.x;    // NTOK*DDIM/2 threads
    if (idx >= NTOK * DDIM / 2) return;
    int w2 = idx & 15;
    int h  = (idx >> 4) & 31;
    int c  = (idx >> 9) & 127;
    int b  = idx >> 16;
    int n  = (b << 8) + ((h >> 1) << 4) + w2;
    int d0 = (c << 2) + ((h & 1) << 1);
    int pr0 = d_tok_pr[n * 2 + 0];
    int pr1 = d_tok_pr[n * 2 + 1];
    float2 a = *(const float2*)&d_po[(size_t)pr0 * DDIM + d0];
    float2 bb = *(const float2*)&d_po[(size_t)pr1 * DDIM + d0];
    size_t yo = ((size_t)(b * CC + c) * HH + h) * WW + w2 * 2;
    *(float2*)(y + yo) = make_float2(a.x + bb.x, a.y + bb.y);
}

// ---------------- launch -----------------------------------------------------
extern "C" void kernel_launch(void* const* d_in, const int* in_sizes, int n_in,
                              void* d_out, int out_size) {
    const float* x  = (const float*)d_in[0];
    const float* rw = (const float*)d_in[1];
    const float* w1 = (const float*)d_in[2];
    const float* w2 = (const float*)d_in[3];
    float* y = (float*)d_out;

    cudaFuncSetAttribute(gemm1_kernel, cudaFuncAttributeMaxDynamicSharedMemorySize, G1_SMEM);
    cudaFuncSetAttribute(gemm2_kernel, cudaFuncAttributeMaxDynamicSharedMemorySize, G2_SMEM);

    f16 *w1h, *w2h;
    cudaGetSymbolAddress((void**)&w1h, d_w1h);
    cudaGetSymbolAddress((void**)&w2h, d_w2h);

    convert_w_kernel<<<1024, 256>>>(w1, w2, w1h, w2h);                        // 0 (+reset)
    router_kernel<<<NTOK / 8, 256>>>(x, rw);                                  // 1 (patchify+router)
    scatter_kernel<<<(NTOK + 255) / 256, 256>>>();                            // 2 (+offsets)
    gemm1_kernel<<<dim3(HID / 64, NTOK / BM, NEXP), 256, G1_SMEM>>>();        // 3 (ncu window)
    gemm2_kernel<<<dim3(DDIM / 128, NTOK / BM, NEXP), 256, G2_SMEM>>>();      // 4
    combine_kernel<<<(NTOK * DDIM / 2 + 255) / 256, 256>>>(y);                // 5
}